// round 4
// baseline (speedup 1.0000x reference)
#include <cuda_runtime.h>
#include <math.h>

#define NN     100000
#define NITEM  80000
#define DD     128
#define DX     64
#define NE     800000
#define NB     4096

// ---------------- device scratch ----------------
__device__ __align__(16) float g_x [(size_t)NN * DD];
__device__ __align__(16) float g_xw[(size_t)NN * DD];
__device__ __align__(16) float g_h [(size_t)NN * DD];   // finalized gat output
__device__ int g_deg[NN];        // out-degree of src
__device__ int g_cnt[NN];        // in-degree of dst (histogram)
__device__ int g_cur[NN];        // build cursors
__device__ int g_off[NN + 1];    // CSR offsets by dst
__device__ int g_csr_src[NE];    // src ids grouped by dst

__device__ __forceinline__ float lrelu(float v) { return v > 0.f ? v : 0.01f * v; }

// ---------------- packed f32x2 helpers (Blackwell FFMA2) ----------------
__device__ __forceinline__ unsigned long long dup2(float a) {
    unsigned long long r;
    asm("mov.b64 %0, {%1, %1};" : "=l"(r) : "r"(__float_as_uint(a)));
    return r;
}
__device__ __forceinline__ void fma2(unsigned long long& d, unsigned long long a,
                                     unsigned long long b) {
    asm("fma.rn.f32x2 %0, %1, %2, %0;" : "+l"(d) : "l"(a), "l"(b));
}
__device__ __forceinline__ float lo32(unsigned long long v) {
    return __uint_as_float((unsigned)v);
}
__device__ __forceinline__ float hi32(unsigned long long v) {
    return __uint_as_float((unsigned)(v >> 32));
}

template <int LDB>
__device__ __forceinline__ void mmtile(const float* __restrict__ As,
                                       const float* __restrict__ Bs,
                                       int r0, int c0, float (&out)[8][8]) {
    unsigned long long acc[8][4];
    #pragma unroll
    for (int r = 0; r < 8; r++) {
        acc[r][0] = 0ull; acc[r][1] = 0ull; acc[r][2] = 0ull; acc[r][3] = 0ull;
    }
    #pragma unroll 1
    for (int k = 0; k < 128; k += 4) {
        float4 av[8];
        #pragma unroll
        for (int r = 0; r < 8; r++)
            av[r] = *(const float4*)(As + (r0 + r) * 128 + k);
        #pragma unroll
        for (int kk = 0; kk < 4; kk++) {
            ulonglong2 b01 = *(const ulonglong2*)(Bs + (k + kk) * LDB + c0);
            ulonglong2 b23 = *(const ulonglong2*)(Bs + (k + kk) * LDB + c0 + 4);
            #pragma unroll
            for (int r = 0; r < 8; r++) {
                float a = (kk == 0) ? av[r].x : (kk == 1) ? av[r].y
                        : (kk == 2) ? av[r].z : av[r].w;
                unsigned long long ad = dup2(a);
                fma2(acc[r][0], ad, b01.x);
                fma2(acc[r][1], ad, b01.y);
                fma2(acc[r][2], ad, b23.x);
                fma2(acc[r][3], ad, b23.y);
            }
        }
    }
    #pragma unroll
    for (int r = 0; r < 8; r++) {
        out[r][0] = lo32(acc[r][0]); out[r][1] = hi32(acc[r][0]);
        out[r][2] = lo32(acc[r][1]); out[r][3] = hi32(acc[r][1]);
        out[r][4] = lo32(acc[r][2]); out[r][5] = hi32(acc[r][2]);
        out[r][6] = lo32(acc[r][3]); out[r][7] = hi32(acc[r][3]);
    }
}

// ---------------- zero counters ----------------
__global__ void k_zero() {
    int i = blockIdx.x * 256 + threadIdx.x;
    if (i < NN) { g_deg[i] = 0; g_cnt[i] = 0; g_cur[i] = 0; }
}

// ---------------- histogram: src out-degree + dst in-degree ----------------
__global__ void k_hist(const int* __restrict__ ei) {
    int e = blockIdx.x * 256 + threadIdx.x;
    if (e < NE) {
        atomicAdd(&g_deg[__ldg(ei + e)], 1);
        atomicAdd(&g_cnt[__ldg(ei + NE + e)], 1);
    }
}

// ---------------- exclusive scan of g_cnt -> g_off (single block) ----------------
__global__ void __launch_bounds__(1024) k_scan() {
    __shared__ int part[1024];
    const int t = threadIdx.x;
    const int per = (NN + 1023) / 1024;
    int s0 = t * per, s1 = s0 + per; if (s1 > NN) s1 = NN;
    int s = 0;
    for (int i = s0; i < s1; i++) s += g_cnt[i];
    part[t] = s;
    __syncthreads();
    #pragma unroll
    for (int off = 1; off < 1024; off <<= 1) {
        int v = (t >= off) ? part[t - off] : 0;
        __syncthreads();
        part[t] += v;
        __syncthreads();
    }
    int base = (t == 0) ? 0 : part[t - 1];
    for (int i = s0; i < s1; i++) { g_off[i] = base; base += g_cnt[i]; }
    if (t == 1023) g_off[NN] = base;
}

// ---------------- CSR build: group src ids by dst ----------------
__global__ void k_build(const int* __restrict__ ei) {
    int e = blockIdx.x * 256 + threadIdx.x;
    if (e >= NE) return;
    int sj = __ldg(ei + e);
    int di = __ldg(ei + NE + e);
    int pos = g_off[di] + atomicAdd(&g_cur[di], 1);
    g_csr_src[pos] = sj;
}

// ---------------- fused GAT aggregation: one warp per dst, 8-edge batches -------------
// h[d] = lrelu(l2norm( (sum_e ev_e * xw[src_e]) / (sum_e ev_e + 1e-16) + bgat ))
__global__ void __launch_bounds__(256) k_aggr(const float* __restrict__ bgat) {
    int gt = blockIdx.x * 256 + threadIdx.x;
    int w = gt >> 5, lane = gt & 31;
    if (w >= NN) return;

    float4 xd = *((const float4*)(g_xw + (size_t)w * DD) + lane);
    int p   = __ldg(&g_off[w]);
    const int end = __ldg(&g_off[w + 1]);

    float4 acc = make_float4(0.f, 0.f, 0.f, 0.f);
    float s = 0.f;

    while (p < end) {
        const int m = min(8, end - p);   // uniform across warp
        int sj[8];
        #pragma unroll
        for (int i = 0; i < 8; i++)
            sj[i] = __ldg(&g_csr_src[p + min(i, m - 1)]);   // clamp tail
        // issue all 8 row loads + 8 degree loads together (MLP 16)
        float4 a[8];
        #pragma unroll
        for (int i = 0; i < 8; i++)
            a[i] = *((const float4*)(g_xw + (size_t)sj[i] * DD) + lane);
        float dg[8];
        #pragma unroll
        for (int i = 0; i < 8; i++)
            dg[i] = (float)__ldg(&g_deg[sj[i]]);

        float d[8];
        #pragma unroll
        for (int i = 0; i < 8; i++)
            d[i] = a[i].x * xd.x + a[i].y * xd.y + a[i].z * xd.z + a[i].w * xd.w;
        // 8 interleaved butterfly reductions (independent chains -> ILP)
        #pragma unroll
        for (int o = 16; o; o >>= 1) {
            #pragma unroll
            for (int i = 0; i < 8; i++)
                d[i] += __shfl_xor_sync(0xffffffffu, d[i], o);
        }
        float ev[8];
        #pragma unroll
        for (int i = 0; i < 8; i++) {
            float gate = 1.f / (1.f + __expf(-rsqrtf(dg[i]) * d[i]));
            ev[i] = __expf(d[i] * gate);
        }
        #pragma unroll
        for (int i = 0; i < 8; i++) {
            float e = (i < m) ? ev[i] : 0.f;
            s += e;
            acc.x += e * a[i].x; acc.y += e * a[i].y;
            acc.z += e * a[i].z; acc.w += e * a[i].w;
        }
        p += m;
    }

    float inv_s = 1.f / (s + 1e-16f);
    float4 bb = __ldg((const float4*)bgat + lane);
    float4 h = make_float4(acc.x * inv_s + bb.x, acc.y * inv_s + bb.y,
                           acc.z * inv_s + bb.z, acc.w * inv_s + bb.w);
    float ss = h.x * h.x + h.y * h.y + h.z * h.z + h.w * h.w;
    #pragma unroll
    for (int o = 16; o; o >>= 1) ss += __shfl_xor_sync(0xffffffffu, ss, o);
    float inv = 1.f / fmaxf(sqrtf(ss), 1e-12f);
    h.x = lrelu(h.x * inv); h.y = lrelu(h.y * inv);
    h.z = lrelu(h.z * inv); h.w = lrelu(h.w * inv);
    *((float4*)(g_h + (size_t)w * DD) + lane) = h;
}

// ---------------- fused: x = l2norm(tanh(feat@W.T+b)); xw = x@W_gat ----------------
__global__ void __launch_bounds__(256, 1) k_gemm_fused(
    const float* __restrict__ feat, const float* __restrict__ ufeat,
    const float* __restrict__ Wm, const float* __restrict__ bm,
    const float* __restrict__ Wu, const float* __restrict__ bu,
    const float* __restrict__ Wg)
{
    extern __shared__ float smx[];
    float* As = smx;            // 128 x 128
    float* Bs = smx + 16384;    // 128 x 128
    const int row0 = blockIdx.x * 128;
    const bool user = row0 >= NITEM;
    const float* A    = user ? (ufeat + (size_t)(row0 - NITEM) * DD)
                             : (feat  + (size_t)row0 * DD);
    const float* W    = user ? Wu : Wm;
    const float* bias = user ? bu : bm;
    int rowlim = NN - row0; if (rowlim > 128) rowlim = 128;
    const int tid = threadIdx.x;

    for (int i = tid; i < 128 * 32; i += 256) {
        int r = i >> 5, c4 = i & 31;
        float4 v = make_float4(0.f, 0.f, 0.f, 0.f);
        if (r < rowlim) v = __ldg((const float4*)A + (size_t)r * 32 + c4);
        *(float4*)&As[r * 128 + c4 * 4] = v;
    }
    for (int i = tid; i < 128 * 32; i += 256) {
        int j = i & 127, c4 = i >> 7;
        float4 v = __ldg((const float4*)W + j * 32 + c4);
        Bs[(c4 * 4 + 0) * 128 + j] = v.x;
        Bs[(c4 * 4 + 1) * 128 + j] = v.y;
        Bs[(c4 * 4 + 2) * 128 + j] = v.z;
        Bs[(c4 * 4 + 3) * 128 + j] = v.w;
    }
    __syncthreads();

    const int ty = tid >> 4, tx = tid & 15;
    const int r0 = ty * 8, c0 = tx * 8;
    float v[8][8];
    mmtile<128>(As, Bs, r0, c0, v);

    float4 bb0 = __ldg((const float4*)(bias + c0));
    float4 bb1 = __ldg((const float4*)(bias + c0 + 4));
    float bcol[8] = {bb0.x, bb0.y, bb0.z, bb0.w, bb1.x, bb1.y, bb1.z, bb1.w};
    #pragma unroll
    for (int r = 0; r < 8; r++) {
        float ss = 0.f;
        #pragma unroll
        for (int c = 0; c < 8; c++) {
            float t = tanhf(v[r][c] + bcol[c]);
            v[r][c] = t; ss += t * t;
        }
        #pragma unroll
        for (int o = 8; o; o >>= 1) ss += __shfl_xor_sync(0xffffffffu, ss, o);
        float inv = 1.f / fmaxf(sqrtf(ss), 1e-12f);
        #pragma unroll
        for (int c = 0; c < 8; c++) v[r][c] *= inv;
        int grow = row0 + r0 + r;
        if (grow < NN) {
            *(float4*)&g_x[(size_t)grow * 128 + c0] =
                make_float4(v[r][0], v[r][1], v[r][2], v[r][3]);
            *(float4*)&g_x[(size_t)grow * 128 + c0 + 4] =
                make_float4(v[r][4], v[r][5], v[r][6], v[r][7]);
        }
    }
    __syncthreads();

    #pragma unroll
    for (int r = 0; r < 8; r++) {
        *(float4*)&As[(r0 + r) * 128 + c0] =
            make_float4(v[r][0], v[r][1], v[r][2], v[r][3]);
        *(float4*)&As[(r0 + r) * 128 + c0 + 4] =
            make_float4(v[r][4], v[r][5], v[r][6], v[r][7]);
    }
    for (int i = tid; i < 128 * 32; i += 256) {
        int kk = i >> 5, c4 = i & 31;
        float4 w = __ldg((const float4*)Wg + kk * 32 + c4);
        *(float4*)&Bs[kk * 128 + c4 * 4] = w;
    }
    __syncthreads();

    mmtile<128>(As, Bs, r0, c0, v);
    #pragma unroll
    for (int r = 0; r < 8; r++) {
        int grow = row0 + r0 + r;
        if (grow < NN) {
            *(float4*)&g_xw[(size_t)grow * 128 + c0] =
                make_float4(v[r][0], v[r][1], v[r][2], v[r][3]);
            *(float4*)&g_xw[(size_t)grow * 128 + c0 + 4] =
                make_float4(v[r][4], v[r][5], v[r][6], v[r][7]);
        }
    }
}

// ---------------- rep = lrelu(h@Wg1.T+bg1 + lrelu(x@Wl1.T+bl1) + id_emb) ----------------
__global__ void __launch_bounds__(256, 1) k_rep(
    const float* __restrict__ Wl1, const float* __restrict__ bl1,
    const float* __restrict__ Wg1, const float* __restrict__ bg1,
    const float* __restrict__ id_emb, float* __restrict__ rep)
{
    extern __shared__ float smx[];
    float* Xs  = smx;            // 128 x 128
    float* Hs  = smx + 16384;    // 128 x 128
    float* W1s = smx + 32768;    // 128 x 64, later epilogue buf
    float* Wgs = smx + 40960;    // 128 x 64
    const int row0 = blockIdx.x * 128;
    int rowlim = NN - row0; if (rowlim > 128) rowlim = 128;
    const int tid = threadIdx.x;

    for (int i = tid; i < 128 * 32; i += 256) {
        int r = i >> 5, c4 = i & 31;
        float4 vx = make_float4(0.f, 0.f, 0.f, 0.f), vh = vx;
        if (r < rowlim) {
            vx = *((const float4*)(g_x + (size_t)(row0 + r) * 128) + c4);
            vh = *((const float4*)(g_h + (size_t)(row0 + r) * 128) + c4);
        }
        *(float4*)&Xs[r * 128 + c4 * 4] = vx;
        *(float4*)&Hs[r * 128 + c4 * 4] = vh;
    }
    for (int i = tid; i < 64 * 32; i += 256) {
        int j = i & 63, c4 = i >> 6;
        float4 v1 = __ldg((const float4*)Wl1 + j * 32 + c4);
        float4 vg = __ldg((const float4*)Wg1 + j * 32 + c4);
        W1s[(c4 * 4 + 0) * 64 + j] = v1.x; W1s[(c4 * 4 + 1) * 64 + j] = v1.y;
        W1s[(c4 * 4 + 2) * 64 + j] = v1.z; W1s[(c4 * 4 + 3) * 64 + j] = v1.w;
        Wgs[(c4 * 4 + 0) * 64 + j] = vg.x; Wgs[(c4 * 4 + 1) * 64 + j] = vg.y;
        Wgs[(c4 * 4 + 2) * 64 + j] = vg.z; Wgs[(c4 * 4 + 3) * 64 + j] = vg.w;
    }
    __syncthreads();

    const int half = tid >> 7, t = tid & 127;
    const int r0 = (t >> 3) * 8, c0 = (t & 7) * 8;
    const float* Ablk = half ? Hs : Xs;
    const float* Wblk = half ? Wgs : W1s;
    float v[8][8];
    mmtile<64>(Ablk, Wblk, r0, c0, v);
    __syncthreads();

    float* buf = W1s;
    if (half == 0) {
        float4 b0 = __ldg((const float4*)(bl1 + c0));
        float4 b1 = __ldg((const float4*)(bl1 + c0 + 4));
        float bc[8] = {b0.x, b0.y, b0.z, b0.w, b1.x, b1.y, b1.z, b1.w};
        #pragma unroll
        for (int r = 0; r < 8; r++) {
            int grow = row0 + r0 + r;
            float4 e0 = make_float4(0.f, 0.f, 0.f, 0.f), e1 = e0;
            if (grow < NN) {
                e0 = __ldg((const float4*)(id_emb + (size_t)grow * 64 + c0));
                e1 = __ldg((const float4*)(id_emb + (size_t)grow * 64 + c0 + 4));
            }
            float em[8] = {e0.x, e0.y, e0.z, e0.w, e1.x, e1.y, e1.z, e1.w};
            #pragma unroll
            for (int c = 0; c < 8; c++)
                buf[(r0 + r) * 64 + c0 + c] = lrelu(v[r][c] + bc[c]) + em[c];
        }
    }
    __syncthreads();
    if (half == 1) {
        float4 b0 = __ldg((const float4*)(bg1 + c0));
        float4 b1 = __ldg((const float4*)(bg1 + c0 + 4));
        float bc[8] = {b0.x, b0.y, b0.z, b0.w, b1.x, b1.y, b1.z, b1.w};
        #pragma unroll
        for (int r = 0; r < 8; r++) {
            int grow = row0 + r0 + r;
            if (grow < NN) {
                float o[8];
                #pragma unroll
                for (int c = 0; c < 8; c++)
                    o[c] = lrelu(v[r][c] + bc[c] + buf[(r0 + r) * 64 + c0 + c]);
                *(float4*)&rep[(size_t)grow * 64 + c0] =
                    make_float4(o[0], o[1], o[2], o[3]);
                *(float4*)&rep[(size_t)grow * 64 + c0 + 4] =
                    make_float4(o[4], o[5], o[6], o[7]);
            }
        }
    }
}

// ---------------- batch head ----------------
__global__ void k_batch(const float* __restrict__ rep,
                        const int* __restrict__ un, const int* __restrict__ pit,
                        const int* __restrict__ nit,
                        const float* __restrict__ Wp1, const float* __restrict__ bp1,
                        const float* __restrict__ Wp2, const float* __restrict__ bp2,
                        float* __restrict__ out_pos, float* __restrict__ out_neg,
                        float* __restrict__ out_pred)
{
    int gt = blockIdx.x * 256 + threadIdx.x;
    int w = gt >> 5, lane = gt & 31;
    if (w >= NB) return;
    int iu = __ldg(un + w), ip = __ldg(pit + w), inn = __ldg(nit + w);
    float u0 = __ldg(rep + (size_t)iu * DX + lane), u1 = __ldg(rep + (size_t)iu * DX + 32 + lane);
    float p0 = __ldg(rep + (size_t)ip * DX + lane), p1 = __ldg(rep + (size_t)ip * DX + 32 + lane);
    float n0 = __ldg(rep + (size_t)inn * DX + lane), n1 = __ldg(rep + (size_t)inn * DX + 32 + lane);
    float ps = u0 * p0 + u1 * p1;
    float ns = u0 * n0 + u1 * n1;
    #pragma unroll
    for (int o = 16; o; o >>= 1) {
        ps += __shfl_xor_sync(0xffffffffu, ps, o);
        ns += __shfl_xor_sync(0xffffffffu, ns, o);
    }
    float h0 = __ldg(bp1 + lane), h1 = __ldg(bp1 + lane + 32);
    #pragma unroll 4
    for (int k = 0; k < 128; k++) {
        float srcv = (k < 32) ? u0 : (k < 64) ? u1 : (k < 96) ? p0 : p1;
        float v = __shfl_sync(0xffffffffu, srcv, k & 31);
        h0 += __ldg(Wp1 + lane * 128 + k) * v;
        h1 += __ldg(Wp1 + (lane + 32) * 128 + k) * v;
    }
    h0 = lrelu(h0); h1 = lrelu(h1);
    float pp = __ldg(Wp2 + lane) * h0 + __ldg(Wp2 + lane + 32) * h1;
    #pragma unroll
    for (int o = 16; o; o >>= 1) pp += __shfl_xor_sync(0xffffffffu, pp, o);
    if (lane == 0) {
        out_pos[w] = ps;
        out_neg[w] = ns;
        out_pred[w] = 1.f / (1.f + __expf(-(pp + __ldg(bp2))));
    }
}

// ---------------- launch ----------------
extern "C" void kernel_launch(void* const* d_in, const int* in_sizes, int n_in,
                              void* d_out, int out_size)
{
    const float* feat   = (const float*)d_in[0];
    const float* ufeat  = (const float*)d_in[1];
    const float* Wm     = (const float*)d_in[2];
    const float* bm     = (const float*)d_in[3];
    const float* Wu     = (const float*)d_in[4];
    const float* bu     = (const float*)d_in[5];
    const float* Wgat   = (const float*)d_in[6];
    const float* bgat   = (const float*)d_in[7];
    const float* Wl1    = (const float*)d_in[8];
    const float* bl1    = (const float*)d_in[9];
    const float* Wg1    = (const float*)d_in[10];
    const float* bg1    = (const float*)d_in[11];
    const float* id_emb = (const float*)d_in[12];
    const float* Wp1    = (const float*)d_in[13];
    const float* bp1    = (const float*)d_in[14];
    const float* Wp2    = (const float*)d_in[15];
    const float* bp2    = (const float*)d_in[16];
    const int*   ei     = (const int*)d_in[17];
    const int*   un     = (const int*)d_in[18];
    const int*   pit    = (const int*)d_in[19];
    const int*   nit    = (const int*)d_in[20];

    float* out      = (float*)d_out;
    float* out_pos  = out;
    float* out_neg  = out + NB;
    float* rep      = out + 2 * NB;
    float* out_pred = out + 2 * NB + (size_t)NN * DX;

    cudaFuncSetAttribute(k_gemm_fused, cudaFuncAttributeMaxDynamicSharedMemorySize, 131072);
    cudaFuncSetAttribute(k_rep,        cudaFuncAttributeMaxDynamicSharedMemorySize, 196608);

    k_zero<<<(NN + 255) / 256, 256>>>();
    k_hist<<<(NE + 255) / 256, 256>>>(ei);
    k_scan<<<1, 1024>>>();
    k_build<<<(NE + 255) / 256, 256>>>(ei);
    k_gemm_fused<<<782, 256, 131072>>>(feat, ufeat, Wm, bm, Wu, bu, Wgat);
    k_aggr<<<(NN * 32 + 255) / 256, 256>>>(bgat);
    k_rep<<<782, 256, 196608>>>(Wl1, bl1, Wg1, bg1, id_emb, rep);
    k_batch<<<NB / 8, 256>>>(rep, un, pit, nit, Wp1, bp1, Wp2, bp2,
                             out_pos, out_neg, out_pred);
}

// round 5
// speedup vs baseline: 1.0042x; 1.0042x over previous
#include <cuda_runtime.h>
#include <math.h>

#define NN     100000
#define NITEM  80000
#define DD     128
#define DX     64
#define NE     800000
#define NB     4096

// ---------------- device scratch ----------------
__device__ __align__(16) float g_x [(size_t)NN * DD];
__device__ __align__(16) float g_xw[(size_t)NN * DD];
__device__ __align__(16) float g_h [(size_t)NN * DD];   // finalized gat output
__device__ int g_deg[NN];        // out-degree of src
__device__ int g_cnt[NN];        // in-degree of dst (histogram)
__device__ int g_cur[NN];        // build cursors
__device__ int g_off[NN + 1];    // CSR offsets by dst
__device__ int g_csr_src[NE];    // src ids grouped by dst

__device__ __forceinline__ float lrelu(float v) { return v > 0.f ? v : 0.01f * v; }

// ---------------- packed f32x2 helpers (Blackwell FFMA2) ----------------
__device__ __forceinline__ unsigned long long dup2(float a) {
    unsigned long long r;
    asm("mov.b64 %0, {%1, %1};" : "=l"(r) : "r"(__float_as_uint(a)));
    return r;
}
__device__ __forceinline__ void fma2(unsigned long long& d, unsigned long long a,
                                     unsigned long long b) {
    asm("fma.rn.f32x2 %0, %1, %2, %0;" : "+l"(d) : "l"(a), "l"(b));
}
__device__ __forceinline__ float lo32(unsigned long long v) {
    return __uint_as_float((unsigned)v);
}
__device__ __forceinline__ float hi32(unsigned long long v) {
    return __uint_as_float((unsigned)(v >> 32));
}

template <int LDB>
__device__ __forceinline__ void mmtile(const float* __restrict__ As,
                                       const float* __restrict__ Bs,
                                       int r0, int c0, float (&out)[8][8]) {
    unsigned long long acc[8][4];
    #pragma unroll
    for (int r = 0; r < 8; r++) {
        acc[r][0] = 0ull; acc[r][1] = 0ull; acc[r][2] = 0ull; acc[r][3] = 0ull;
    }
    #pragma unroll 1
    for (int k = 0; k < 128; k += 4) {
        float4 av[8];
        #pragma unroll
        for (int r = 0; r < 8; r++)
            av[r] = *(const float4*)(As + (r0 + r) * 128 + k);
        #pragma unroll
        for (int kk = 0; kk < 4; kk++) {
            ulonglong2 b01 = *(const ulonglong2*)(Bs + (k + kk) * LDB + c0);
            ulonglong2 b23 = *(const ulonglong2*)(Bs + (k + kk) * LDB + c0 + 4);
            #pragma unroll
            for (int r = 0; r < 8; r++) {
                float a = (kk == 0) ? av[r].x : (kk == 1) ? av[r].y
                        : (kk == 2) ? av[r].z : av[r].w;
                unsigned long long ad = dup2(a);
                fma2(acc[r][0], ad, b01.x);
                fma2(acc[r][1], ad, b01.y);
                fma2(acc[r][2], ad, b23.x);
                fma2(acc[r][3], ad, b23.y);
            }
        }
    }
    #pragma unroll
    for (int r = 0; r < 8; r++) {
        out[r][0] = lo32(acc[r][0]); out[r][1] = hi32(acc[r][0]);
        out[r][2] = lo32(acc[r][1]); out[r][3] = hi32(acc[r][1]);
        out[r][4] = lo32(acc[r][2]); out[r][5] = hi32(acc[r][2]);
        out[r][6] = lo32(acc[r][3]); out[r][7] = hi32(acc[r][3]);
    }
}

// ---------------- zero counters ----------------
__global__ void k_zero() {
    int i = blockIdx.x * 256 + threadIdx.x;
    if (i < NN) { g_deg[i] = 0; g_cnt[i] = 0; g_cur[i] = 0; }
}

// ---------------- histogram: src out-degree + dst in-degree ----------------
__global__ void k_hist(const int* __restrict__ ei) {
    int e = blockIdx.x * 256 + threadIdx.x;
    if (e < NE) {
        atomicAdd(&g_deg[__ldg(ei + e)], 1);
        atomicAdd(&g_cnt[__ldg(ei + NE + e)], 1);
    }
}

// ---------------- exclusive scan of g_cnt -> g_off (single block) ----------------
__global__ void __launch_bounds__(1024) k_scan() {
    __shared__ int part[1024];
    const int t = threadIdx.x;
    const int per = (NN + 1023) / 1024;
    int s0 = t * per, s1 = s0 + per; if (s1 > NN) s1 = NN;
    int s = 0;
    for (int i = s0; i < s1; i++) s += g_cnt[i];
    part[t] = s;
    __syncthreads();
    #pragma unroll
    for (int off = 1; off < 1024; off <<= 1) {
        int v = (t >= off) ? part[t - off] : 0;
        __syncthreads();
        part[t] += v;
        __syncthreads();
    }
    int base = (t == 0) ? 0 : part[t - 1];
    for (int i = s0; i < s1; i++) { g_off[i] = base; base += g_cnt[i]; }
    if (t == 1023) g_off[NN] = base;
}

// ---------------- CSR build: group src ids by dst ----------------
__global__ void k_build(const int* __restrict__ ei) {
    int e = blockIdx.x * 256 + threadIdx.x;
    if (e >= NE) return;
    int sj = __ldg(ei + e);
    int di = __ldg(ei + NE + e);
    int pos = g_off[di] + atomicAdd(&g_cur[di], 1);
    g_csr_src[pos] = sj;
}

// ---------------- fused GAT aggregation: warp = 4 groups x 8 lanes, 1 edge/group ------
// h[d] = lrelu(l2norm( (sum_e ev_e * xw[src_e]) / (sum_e ev_e + 1e-16) + bgat ))
__global__ void __launch_bounds__(256) k_aggr(const float* __restrict__ bgat) {
    int gt = blockIdx.x * 256 + threadIdx.x;
    int w = gt >> 5;
    if (w >= NN) return;
    const int lane = threadIdx.x & 31;
    const int g = lane >> 3, l = lane & 7;

    // this lane holds dims [l*16, l*16+16) -- identical assignment in every group
    const float4* xdp = (const float4*)(g_xw + (size_t)w * DD + l * 16);
    float4 xd0 = xdp[0], xd1 = xdp[1], xd2 = xdp[2], xd3 = xdp[3];

    int p = __ldg(&g_off[w]);
    const int end = __ldg(&g_off[w + 1]);

    float4 ac0 = make_float4(0.f,0.f,0.f,0.f), ac1 = ac0, ac2 = ac0, ac3 = ac0;
    float s = 0.f;

    float4 r0, r1, r2, r3; float dg;
    if (p < end) {
        int sj = __ldg(&g_csr_src[min(p + g, end - 1)]);
        const float4* rp = (const float4*)(g_xw + (size_t)sj * DD + l * 16);
        r0 = rp[0]; r1 = rp[1]; r2 = rp[2]; r3 = rp[3];
        dg = (float)__ldg(&g_deg[sj]);
    }
    while (p < end) {
        const int pn = p + 4;
        float4 n0, n1, n2, n3; float dgn;
        if (pn < end) {
            int sjn = __ldg(&g_csr_src[min(pn + g, end - 1)]);
            const float4* rp = (const float4*)(g_xw + (size_t)sjn * DD + l * 16);
            n0 = rp[0]; n1 = rp[1]; n2 = rp[2]; n3 = rp[3];
            dgn = (float)__ldg(&g_deg[sjn]);
        }
        // 16-dim partial dot, then 3-deep butterfly within the 8-lane group
        float d = r0.x*xd0.x + r0.y*xd0.y + r0.z*xd0.z + r0.w*xd0.w
                + r1.x*xd1.x + r1.y*xd1.y + r1.z*xd1.z + r1.w*xd1.w
                + r2.x*xd2.x + r2.y*xd2.y + r2.z*xd2.z + r2.w*xd2.w
                + r3.x*xd3.x + r3.y*xd3.y + r3.z*xd3.z + r3.w*xd3.w;
        d += __shfl_xor_sync(0xffffffffu, d, 1);
        d += __shfl_xor_sync(0xffffffffu, d, 2);
        d += __shfl_xor_sync(0xffffffffu, d, 4);
        float gate = 1.f / (1.f + __expf(-rsqrtf(dg) * d));
        float ev = ((p + g) < end) ? __expf(d * gate) : 0.f;
        s += ev;
        ac0.x += ev*r0.x; ac0.y += ev*r0.y; ac0.z += ev*r0.z; ac0.w += ev*r0.w;
        ac1.x += ev*r1.x; ac1.y += ev*r1.y; ac1.z += ev*r1.z; ac1.w += ev*r1.w;
        ac2.x += ev*r2.x; ac2.y += ev*r2.y; ac2.z += ev*r2.z; ac2.w += ev*r2.w;
        ac3.x += ev*r3.x; ac3.y += ev*r3.y; ac3.z += ev*r3.z; ac3.w += ev*r3.w;
        r0 = n0; r1 = n1; r2 = n2; r3 = n3; dg = dgn;
        p = pn;
    }

    // merge the 4 groups (same dim layout): butterfly over lane bits 3,4
    #pragma unroll
    for (int o = 8; o <= 16; o <<= 1) {
        s += __shfl_xor_sync(0xffffffffu, s, o);
        ac0.x += __shfl_xor_sync(0xffffffffu, ac0.x, o);
        ac0.y += __shfl_xor_sync(0xffffffffu, ac0.y, o);
        ac0.z += __shfl_xor_sync(0xffffffffu, ac0.z, o);
        ac0.w += __shfl_xor_sync(0xffffffffu, ac0.w, o);
        ac1.x += __shfl_xor_sync(0xffffffffu, ac1.x, o);
        ac1.y += __shfl_xor_sync(0xffffffffu, ac1.y, o);
        ac1.z += __shfl_xor_sync(0xffffffffu, ac1.z, o);
        ac1.w += __shfl_xor_sync(0xffffffffu, ac1.w, o);
        ac2.x += __shfl_xor_sync(0xffffffffu, ac2.x, o);
        ac2.y += __shfl_xor_sync(0xffffffffu, ac2.y, o);
        ac2.z += __shfl_xor_sync(0xffffffffu, ac2.z, o);
        ac2.w += __shfl_xor_sync(0xffffffffu, ac2.w, o);
        ac3.x += __shfl_xor_sync(0xffffffffu, ac3.x, o);
        ac3.y += __shfl_xor_sync(0xffffffffu, ac3.y, o);
        ac3.z += __shfl_xor_sync(0xffffffffu, ac3.z, o);
        ac3.w += __shfl_xor_sync(0xffffffffu, ac3.w, o);
    }

    float inv_s = 1.f / (s + 1e-16f);
    const float4* bp = (const float4*)(bgat + l * 16);
    float4 b0 = __ldg(bp), b1 = __ldg(bp + 1), b2 = __ldg(bp + 2), b3 = __ldg(bp + 3);
    float4 h0 = make_float4(ac0.x*inv_s + b0.x, ac0.y*inv_s + b0.y,
                            ac0.z*inv_s + b0.z, ac0.w*inv_s + b0.w);
    float4 h1 = make_float4(ac1.x*inv_s + b1.x, ac1.y*inv_s + b1.y,
                            ac1.z*inv_s + b1.z, ac1.w*inv_s + b1.w);
    float4 h2 = make_float4(ac2.x*inv_s + b2.x, ac2.y*inv_s + b2.y,
                            ac2.z*inv_s + b2.z, ac2.w*inv_s + b2.w);
    float4 h3 = make_float4(ac3.x*inv_s + b3.x, ac3.y*inv_s + b3.y,
                            ac3.z*inv_s + b3.z, ac3.w*inv_s + b3.w);
    float ss = h0.x*h0.x + h0.y*h0.y + h0.z*h0.z + h0.w*h0.w
             + h1.x*h1.x + h1.y*h1.y + h1.z*h1.z + h1.w*h1.w
             + h2.x*h2.x + h2.y*h2.y + h2.z*h2.z + h2.w*h2.w
             + h3.x*h3.x + h3.y*h3.y + h3.z*h3.z + h3.w*h3.w;
    ss += __shfl_xor_sync(0xffffffffu, ss, 1);
    ss += __shfl_xor_sync(0xffffffffu, ss, 2);
    ss += __shfl_xor_sync(0xffffffffu, ss, 4);
    float inv = 1.f / fmaxf(sqrtf(ss), 1e-12f);
    if (g == 0) {
        float4* hp = (float4*)(g_h + (size_t)w * DD + l * 16);
        hp[0] = make_float4(lrelu(h0.x*inv), lrelu(h0.y*inv), lrelu(h0.z*inv), lrelu(h0.w*inv));
        hp[1] = make_float4(lrelu(h1.x*inv), lrelu(h1.y*inv), lrelu(h1.z*inv), lrelu(h1.w*inv));
        hp[2] = make_float4(lrelu(h2.x*inv), lrelu(h2.y*inv), lrelu(h2.z*inv), lrelu(h2.w*inv));
        hp[3] = make_float4(lrelu(h3.x*inv), lrelu(h3.y*inv), lrelu(h3.z*inv), lrelu(h3.w*inv));
    }
}

// ---------------- fused: x = l2norm(tanh(feat@W.T+b)); xw = x@W_gat ----------------
__global__ void __launch_bounds__(256, 1) k_gemm_fused(
    const float* __restrict__ feat, const float* __restrict__ ufeat,
    const float* __restrict__ Wm, const float* __restrict__ bm,
    const float* __restrict__ Wu, const float* __restrict__ bu,
    const float* __restrict__ Wg)
{
    extern __shared__ float smx[];
    float* As = smx;            // 128 x 128
    float* Bs = smx + 16384;    // 128 x 128
    const int row0 = blockIdx.x * 128;
    const bool user = row0 >= NITEM;
    const float* A    = user ? (ufeat + (size_t)(row0 - NITEM) * DD)
                             : (feat  + (size_t)row0 * DD);
    const float* W    = user ? Wu : Wm;
    const float* bias = user ? bu : bm;
    int rowlim = NN - row0; if (rowlim > 128) rowlim = 128;
    const int tid = threadIdx.x;

    for (int i = tid; i < 128 * 32; i += 256) {
        int r = i >> 5, c4 = i & 31;
        float4 v = make_float4(0.f, 0.f, 0.f, 0.f);
        if (r < rowlim) v = __ldg((const float4*)A + (size_t)r * 32 + c4);
        *(float4*)&As[r * 128 + c4 * 4] = v;
    }
    for (int i = tid; i < 128 * 32; i += 256) {
        int j = i & 127, c4 = i >> 7;
        float4 v = __ldg((const float4*)W + j * 32 + c4);
        Bs[(c4 * 4 + 0) * 128 + j] = v.x;
        Bs[(c4 * 4 + 1) * 128 + j] = v.y;
        Bs[(c4 * 4 + 2) * 128 + j] = v.z;
        Bs[(c4 * 4 + 3) * 128 + j] = v.w;
    }
    __syncthreads();

    const int ty = tid >> 4, tx = tid & 15;
    const int r0 = ty * 8, c0 = tx * 8;
    float v[8][8];
    mmtile<128>(As, Bs, r0, c0, v);

    float4 bb0 = __ldg((const float4*)(bias + c0));
    float4 bb1 = __ldg((const float4*)(bias + c0 + 4));
    float bcol[8] = {bb0.x, bb0.y, bb0.z, bb0.w, bb1.x, bb1.y, bb1.z, bb1.w};
    #pragma unroll
    for (int r = 0; r < 8; r++) {
        float ss = 0.f;
        #pragma unroll
        for (int c = 0; c < 8; c++) {
            float t = tanhf(v[r][c] + bcol[c]);
            v[r][c] = t; ss += t * t;
        }
        #pragma unroll
        for (int o = 8; o; o >>= 1) ss += __shfl_xor_sync(0xffffffffu, ss, o);
        float inv = 1.f / fmaxf(sqrtf(ss), 1e-12f);
        #pragma unroll
        for (int c = 0; c < 8; c++) v[r][c] *= inv;
        int grow = row0 + r0 + r;
        if (grow < NN) {
            *(float4*)&g_x[(size_t)grow * 128 + c0] =
                make_float4(v[r][0], v[r][1], v[r][2], v[r][3]);
            *(float4*)&g_x[(size_t)grow * 128 + c0 + 4] =
                make_float4(v[r][4], v[r][5], v[r][6], v[r][7]);
        }
    }
    __syncthreads();

    #pragma unroll
    for (int r = 0; r < 8; r++) {
        *(float4*)&As[(r0 + r) * 128 + c0] =
            make_float4(v[r][0], v[r][1], v[r][2], v[r][3]);
        *(float4*)&As[(r0 + r) * 128 + c0 + 4] =
            make_float4(v[r][4], v[r][5], v[r][6], v[r][7]);
    }
    for (int i = tid; i < 128 * 32; i += 256) {
        int kk = i >> 5, c4 = i & 31;
        float4 w = __ldg((const float4*)Wg + kk * 32 + c4);
        *(float4*)&Bs[kk * 128 + c4 * 4] = w;
    }
    __syncthreads();

    mmtile<128>(As, Bs, r0, c0, v);
    #pragma unroll
    for (int r = 0; r < 8; r++) {
        int grow = row0 + r0 + r;
        if (grow < NN) {
            *(float4*)&g_xw[(size_t)grow * 128 + c0] =
                make_float4(v[r][0], v[r][1], v[r][2], v[r][3]);
            *(float4*)&g_xw[(size_t)grow * 128 + c0 + 4] =
                make_float4(v[r][4], v[r][5], v[r][6], v[r][7]);
        }
    }
}

// ---------------- rep = lrelu(h@Wg1.T+bg1 + lrelu(x@Wl1.T+bl1) + id_emb) ----------------
__global__ void __launch_bounds__(256, 1) k_rep(
    const float* __restrict__ Wl1, const float* __restrict__ bl1,
    const float* __restrict__ Wg1, const float* __restrict__ bg1,
    const float* __restrict__ id_emb, float* __restrict__ rep)
{
    extern __shared__ float smx[];
    float* Xs  = smx;            // 128 x 128
    float* Hs  = smx + 16384;    // 128 x 128
    float* W1s = smx + 32768;    // 128 x 64, later epilogue buf
    float* Wgs = smx + 40960;    // 128 x 64
    const int row0 = blockIdx.x * 128;
    int rowlim = NN - row0; if (rowlim > 128) rowlim = 128;
    const int tid = threadIdx.x;

    for (int i = tid; i < 128 * 32; i += 256) {
        int r = i >> 5, c4 = i & 31;
        float4 vx = make_float4(0.f, 0.f, 0.f, 0.f), vh = vx;
        if (r < rowlim) {
            vx = *((const float4*)(g_x + (size_t)(row0 + r) * 128) + c4);
            vh = *((const float4*)(g_h + (size_t)(row0 + r) * 128) + c4);
        }
        *(float4*)&Xs[r * 128 + c4 * 4] = vx;
        *(float4*)&Hs[r * 128 + c4 * 4] = vh;
    }
    for (int i = tid; i < 64 * 32; i += 256) {
        int j = i & 63, c4 = i >> 6;
        float4 v1 = __ldg((const float4*)Wl1 + j * 32 + c4);
        float4 vg = __ldg((const float4*)Wg1 + j * 32 + c4);
        W1s[(c4 * 4 + 0) * 64 + j] = v1.x; W1s[(c4 * 4 + 1) * 64 + j] = v1.y;
        W1s[(c4 * 4 + 2) * 64 + j] = v1.z; W1s[(c4 * 4 + 3) * 64 + j] = v1.w;
        Wgs[(c4 * 4 + 0) * 64 + j] = vg.x; Wgs[(c4 * 4 + 1) * 64 + j] = vg.y;
        Wgs[(c4 * 4 + 2) * 64 + j] = vg.z; Wgs[(c4 * 4 + 3) * 64 + j] = vg.w;
    }
    __syncthreads();

    const int half = tid >> 7, t = tid & 127;
    const int r0 = (t >> 3) * 8, c0 = (t & 7) * 8;
    const float* Ablk = half ? Hs : Xs;
    const float* Wblk = half ? Wgs : W1s;
    float v[8][8];
    mmtile<64>(Ablk, Wblk, r0, c0, v);
    __syncthreads();

    float* buf = W1s;
    if (half == 0) {
        float4 b0 = __ldg((const float4*)(bl1 + c0));
        float4 b1 = __ldg((const float4*)(bl1 + c0 + 4));
        float bc[8] = {b0.x, b0.y, b0.z, b0.w, b1.x, b1.y, b1.z, b1.w};
        #pragma unroll
        for (int r = 0; r < 8; r++) {
            int grow = row0 + r0 + r;
            float4 e0 = make_float4(0.f, 0.f, 0.f, 0.f), e1 = e0;
            if (grow < NN) {
                e0 = __ldg((const float4*)(id_emb + (size_t)grow * 64 + c0));
                e1 = __ldg((const float4*)(id_emb + (size_t)grow * 64 + c0 + 4));
            }
            float em[8] = {e0.x, e0.y, e0.z, e0.w, e1.x, e1.y, e1.z, e1.w};
            #pragma unroll
            for (int c = 0; c < 8; c++)
                buf[(r0 + r) * 64 + c0 + c] = lrelu(v[r][c] + bc[c]) + em[c];
        }
    }
    __syncthreads();
    if (half == 1) {
        float4 b0 = __ldg((const float4*)(bg1 + c0));
        float4 b1 = __ldg((const float4*)(bg1 + c0 + 4));
        float bc[8] = {b0.x, b0.y, b0.z, b0.w, b1.x, b1.y, b1.z, b1.w};
        #pragma unroll
        for (int r = 0; r < 8; r++) {
            int grow = row0 + r0 + r;
            if (grow < NN) {
                float o[8];
                #pragma unroll
                for (int c = 0; c < 8; c++)
                    o[c] = lrelu(v[r][c] + bc[c] + buf[(r0 + r) * 64 + c0 + c]);
                *(float4*)&rep[(size_t)grow * 64 + c0] =
                    make_float4(o[0], o[1], o[2], o[3]);
                *(float4*)&rep[(size_t)grow * 64 + c0 + 4] =
                    make_float4(o[4], o[5], o[6], o[7]);
            }
        }
    }
}

// ---------------- batch head ----------------
__global__ void k_batch(const float* __restrict__ rep,
                        const int* __restrict__ un, const int* __restrict__ pit,
                        const int* __restrict__ nit,
                        const float* __restrict__ Wp1, const float* __restrict__ bp1,
                        const float* __restrict__ Wp2, const float* __restrict__ bp2,
                        float* __restrict__ out_pos, float* __restrict__ out_neg,
                        float* __restrict__ out_pred)
{
    int gt = blockIdx.x * 256 + threadIdx.x;
    int w = gt >> 5, lane = gt & 31;
    if (w >= NB) return;
    int iu = __ldg(un + w), ip = __ldg(pit + w), inn = __ldg(nit + w);
    float u0 = __ldg(rep + (size_t)iu * DX + lane), u1 = __ldg(rep + (size_t)iu * DX + 32 + lane);
    float p0 = __ldg(rep + (size_t)ip * DX + lane), p1 = __ldg(rep + (size_t)ip * DX + 32 + lane);
    float n0 = __ldg(rep + (size_t)inn * DX + lane), n1 = __ldg(rep + (size_t)inn * DX + 32 + lane);
    float ps = u0 * p0 + u1 * p1;
    float ns = u0 * n0 + u1 * n1;
    #pragma unroll
    for (int o = 16; o; o >>= 1) {
        ps += __shfl_xor_sync(0xffffffffu, ps, o);
        ns += __shfl_xor_sync(0xffffffffu, ns, o);
    }
    float h0 = __ldg(bp1 + lane), h1 = __ldg(bp1 + lane + 32);
    #pragma unroll 4
    for (int k = 0; k < 128; k++) {
        float srcv = (k < 32) ? u0 : (k < 64) ? u1 : (k < 96) ? p0 : p1;
        float v = __shfl_sync(0xffffffffu, srcv, k & 31);
        h0 += __ldg(Wp1 + lane * 128 + k) * v;
        h1 += __ldg(Wp1 + (lane + 32) * 128 + k) * v;
    }
    h0 = lrelu(h0); h1 = lrelu(h1);
    float pp = __ldg(Wp2 + lane) * h0 + __ldg(Wp2 + lane + 32) * h1;
    #pragma unroll
    for (int o = 16; o; o >>= 1) pp += __shfl_xor_sync(0xffffffffu, pp, o);
    if (lane == 0) {
        out_pos[w] = ps;
        out_neg[w] = ns;
        out_pred[w] = 1.f / (1.f + __expf(-(pp + __ldg(bp2))));
    }
}

// ---------------- launch ----------------
extern "C" void kernel_launch(void* const* d_in, const int* in_sizes, int n_in,
                              void* d_out, int out_size)
{
    const float* feat   = (const float*)d_in[0];
    const float* ufeat  = (const float*)d_in[1];
    const float* Wm     = (const float*)d_in[2];
    const float* bm     = (const float*)d_in[3];
    const float* Wu     = (const float*)d_in[4];
    const float* bu     = (const float*)d_in[5];
    const float* Wgat   = (const float*)d_in[6];
    const float* bgat   = (const float*)d_in[7];
    const float* Wl1    = (const float*)d_in[8];
    const float* bl1    = (const float*)d_in[9];
    const float* Wg1    = (const float*)d_in[10];
    const float* bg1    = (const float*)d_in[11];
    const float* id_emb = (const float*)d_in[12];
    const float* Wp1    = (const float*)d_in[13];
    const float* bp1    = (const float*)d_in[14];
    const float* Wp2    = (const float*)d_in[15];
    const float* bp2    = (const float*)d_in[16];
    const int*   ei     = (const int*)d_in[17];
    const int*   un     = (const int*)d_in[18];
    const int*   pit    = (const int*)d_in[19];
    const int*   nit    = (const int*)d_in[20];

    float* out      = (float*)d_out;
    float* out_pos  = out;
    float* out_neg  = out + NB;
    float* rep      = out + 2 * NB;
    float* out_pred = out + 2 * NB + (size_t)NN * DX;

    cudaFuncSetAttribute(k_gemm_fused, cudaFuncAttributeMaxDynamicSharedMemorySize, 131072);
    cudaFuncSetAttribute(k_rep,        cudaFuncAttributeMaxDynamicSharedMemorySize, 196608);

    k_zero<<<(NN + 255) / 256, 256>>>();
    k_hist<<<(NE + 255) / 256, 256>>>(ei);
    k_scan<<<1, 1024>>>();
    k_build<<<(NE + 255) / 256, 256>>>(ei);
    k_gemm_fused<<<782, 256, 131072>>>(feat, ufeat, Wm, bm, Wu, bu, Wgat);
    k_aggr<<<(NN * 32 + 255) / 256, 256>>>(bgat);
    k_rep<<<782, 256, 196608>>>(Wl1, bl1, Wg1, bg1, id_emb, rep);
    k_batch<<<NB / 8, 256>>>(rep, un, pit, nit, Wp1, bp1, Wp2, bp2,
                             out_pos, out_neg, out_pred);
}

// round 6
// speedup vs baseline: 1.0995x; 1.0949x over previous
#include <cuda_runtime.h>
#include <math.h>

#define NN     100000
#define NITEM  80000
#define DD     128
#define DX     64
#define NE     800000
#define NB     4096

// ---------------- device scratch ----------------
__device__ __align__(16) float g_x [(size_t)NN * DD];
__device__ __align__(16) float g_xw[(size_t)NN * DD];
__device__ __align__(16) float g_h [(size_t)NN * DD];   // finalized gat output
__device__ int g_deg[NN];        // out-degree of src
__device__ int g_cnt[NN];        // in-degree of dst (histogram)
__device__ int g_cur[NN];        // build cursors
__device__ int g_off[NN + 1];    // CSR offsets by dst
__device__ int g_csr_src[NE];    // src ids grouped by dst

__device__ __forceinline__ float lrelu(float v) { return v > 0.f ? v : 0.01f * v; }

// ---------------- packed f32x2 helpers (Blackwell FFMA2) ----------------
__device__ __forceinline__ unsigned long long dup2(float a) {
    unsigned long long r;
    asm("mov.b64 %0, {%1, %1};" : "=l"(r) : "r"(__float_as_uint(a)));
    return r;
}
__device__ __forceinline__ void fma2(unsigned long long& d, unsigned long long a,
                                     unsigned long long b) {
    asm("fma.rn.f32x2 %0, %1, %2, %0;" : "+l"(d) : "l"(a), "l"(b));
}
__device__ __forceinline__ float lo32(unsigned long long v) {
    return __uint_as_float((unsigned)v);
}
__device__ __forceinline__ float hi32(unsigned long long v) {
    return __uint_as_float((unsigned)(v >> 32));
}

template <int LDB>
__device__ __forceinline__ void mmtile(const float* __restrict__ As,
                                       const float* __restrict__ Bs,
                                       int r0, int c0, float (&out)[8][8]) {
    unsigned long long acc[8][4];
    #pragma unroll
    for (int r = 0; r < 8; r++) {
        acc[r][0] = 0ull; acc[r][1] = 0ull; acc[r][2] = 0ull; acc[r][3] = 0ull;
    }
    #pragma unroll 1
    for (int k = 0; k < 128; k += 4) {
        float4 av[8];
        #pragma unroll
        for (int r = 0; r < 8; r++)
            av[r] = *(const float4*)(As + (r0 + r) * 128 + k);
        #pragma unroll
        for (int kk = 0; kk < 4; kk++) {
            ulonglong2 b01 = *(const ulonglong2*)(Bs + (k + kk) * LDB + c0);
            ulonglong2 b23 = *(const ulonglong2*)(Bs + (k + kk) * LDB + c0 + 4);
            #pragma unroll
            for (int r = 0; r < 8; r++) {
                float a = (kk == 0) ? av[r].x : (kk == 1) ? av[r].y
                        : (kk == 2) ? av[r].z : av[r].w;
                unsigned long long ad = dup2(a);
                fma2(acc[r][0], ad, b01.x);
                fma2(acc[r][1], ad, b01.y);
                fma2(acc[r][2], ad, b23.x);
                fma2(acc[r][3], ad, b23.y);
            }
        }
    }
    #pragma unroll
    for (int r = 0; r < 8; r++) {
        out[r][0] = lo32(acc[r][0]); out[r][1] = hi32(acc[r][0]);
        out[r][2] = lo32(acc[r][1]); out[r][3] = hi32(acc[r][1]);
        out[r][4] = lo32(acc[r][2]); out[r][5] = hi32(acc[r][2]);
        out[r][6] = lo32(acc[r][3]); out[r][7] = hi32(acc[r][3]);
    }
}

// ---------------- zero counters ----------------
__global__ void k_zero() {
    int i = blockIdx.x * 256 + threadIdx.x;
    if (i < NN) { g_deg[i] = 0; g_cnt[i] = 0; g_cur[i] = 0; }
}

// ---------------- histogram: src out-degree + dst in-degree ----------------
__global__ void k_hist(const int* __restrict__ ei) {
    int e = blockIdx.x * 256 + threadIdx.x;
    if (e < NE) {
        atomicAdd(&g_deg[__ldg(ei + e)], 1);
        atomicAdd(&g_cnt[__ldg(ei + NE + e)], 1);
    }
}

// ---------------- exclusive scan of g_cnt -> g_off (single block) ----------------
__global__ void __launch_bounds__(1024) k_scan() {
    __shared__ int part[1024];
    const int t = threadIdx.x;
    const int per = (NN + 1023) / 1024;
    int s0 = t * per, s1 = s0 + per; if (s1 > NN) s1 = NN;
    int s = 0;
    for (int i = s0; i < s1; i++) s += g_cnt[i];
    part[t] = s;
    __syncthreads();
    #pragma unroll
    for (int off = 1; off < 1024; off <<= 1) {
        int v = (t >= off) ? part[t - off] : 0;
        __syncthreads();
        part[t] += v;
        __syncthreads();
    }
    int base = (t == 0) ? 0 : part[t - 1];
    for (int i = s0; i < s1; i++) { g_off[i] = base; base += g_cnt[i]; }
    if (t == 1023) g_off[NN] = base;
}

// ---------------- CSR build: group src ids by dst ----------------
__global__ void k_build(const int* __restrict__ ei) {
    int e = blockIdx.x * 256 + threadIdx.x;
    if (e >= NE) return;
    int sj = __ldg(ei + e);
    int di = __ldg(ei + NE + e);
    int pos = g_off[di] + atomicAdd(&g_cur[di], 1);
    g_csr_src[pos] = sj;
}

// ---------------- fused GAT aggregation: one warp per dst node (R3 version) ----------
// h[d] = lrelu(l2norm( (sum_e ev_e * xw[src_e]) / (sum_e ev_e + 1e-16) + bgat ))
__global__ void __launch_bounds__(256) k_aggr(const float* __restrict__ bgat) {
    int gt = blockIdx.x * 256 + threadIdx.x;
    int w = gt >> 5, lane = gt & 31;
    if (w >= NN) return;

    float4 xd = *((const float4*)(g_xw + (size_t)w * DD) + lane);
    int p   = __ldg(&g_off[w]);
    int end = __ldg(&g_off[w + 1]);

    float4 acc = make_float4(0.f, 0.f, 0.f, 0.f);
    float s = 0.f;

    float4 a; float dg;
    if (p < end) {
        int sj = __ldg(&g_csr_src[p]);
        a  = *((const float4*)(g_xw + (size_t)sj * DD) + lane);
        dg = (float)__ldg(&g_deg[sj]);
    }
    while (p < end) {
        float4 a_n; float dg_n;
        if (p + 1 < end) {
            int sj = __ldg(&g_csr_src[p + 1]);
            a_n  = *((const float4*)(g_xw + (size_t)sj * DD) + lane);
            dg_n = (float)__ldg(&g_deg[sj]);
        }
        float d = a.x * xd.x + a.y * xd.y + a.z * xd.z + a.w * xd.w;
        #pragma unroll
        for (int o = 16; o; o >>= 1) d += __shfl_xor_sync(0xffffffffu, d, o);
        float gate = 1.f / (1.f + __expf(-rsqrtf(dg) * d));
        float ev = __expf(d * gate);
        s += ev;
        acc.x += ev * a.x; acc.y += ev * a.y;
        acc.z += ev * a.z; acc.w += ev * a.w;
        a = a_n; dg = dg_n; p++;
    }

    float inv_s = 1.f / (s + 1e-16f);
    float4 bb = __ldg((const float4*)bgat + lane);
    float4 h = make_float4(acc.x * inv_s + bb.x, acc.y * inv_s + bb.y,
                           acc.z * inv_s + bb.z, acc.w * inv_s + bb.w);
    float ss = h.x * h.x + h.y * h.y + h.z * h.z + h.w * h.w;
    #pragma unroll
    for (int o = 16; o; o >>= 1) ss += __shfl_xor_sync(0xffffffffu, ss, o);
    float inv = 1.f / fmaxf(sqrtf(ss), 1e-12f);
    h.x = lrelu(h.x * inv); h.y = lrelu(h.y * inv);
    h.z = lrelu(h.z * inv); h.w = lrelu(h.w * inv);
    *((float4*)(g_h + (size_t)w * DD) + lane) = h;
}

// ---------------- fused: x = l2norm(tanh(feat@W.T+b)); xw = x@W_gat ----------------
__global__ void __launch_bounds__(256, 1) k_gemm_fused(
    const float* __restrict__ feat, const float* __restrict__ ufeat,
    const float* __restrict__ Wm, const float* __restrict__ bm,
    const float* __restrict__ Wu, const float* __restrict__ bu,
    const float* __restrict__ Wg)
{
    extern __shared__ float smx[];
    float* As = smx;            // 128 x 128
    float* Bs = smx + 16384;    // 128 x 128
    const int row0 = blockIdx.x * 128;
    const bool user = row0 >= NITEM;
    const float* A    = user ? (ufeat + (size_t)(row0 - NITEM) * DD)
                             : (feat  + (size_t)row0 * DD);
    const float* W    = user ? Wu : Wm;
    const float* bias = user ? bu : bm;
    int rowlim = NN - row0; if (rowlim > 128) rowlim = 128;
    const int tid = threadIdx.x;

    for (int i = tid; i < 128 * 32; i += 256) {
        int r = i >> 5, c4 = i & 31;
        float4 v = make_float4(0.f, 0.f, 0.f, 0.f);
        if (r < rowlim) v = __ldg((const float4*)A + (size_t)r * 32 + c4);
        *(float4*)&As[r * 128 + c4 * 4] = v;
    }
    for (int i = tid; i < 128 * 32; i += 256) {
        int j = i & 127, c4 = i >> 7;
        float4 v = __ldg((const float4*)W + j * 32 + c4);
        Bs[(c4 * 4 + 0) * 128 + j] = v.x;
        Bs[(c4 * 4 + 1) * 128 + j] = v.y;
        Bs[(c4 * 4 + 2) * 128 + j] = v.z;
        Bs[(c4 * 4 + 3) * 128 + j] = v.w;
    }
    __syncthreads();

    const int ty = tid >> 4, tx = tid & 15;
    const int r0 = ty * 8, c0 = tx * 8;
    float v[8][8];
    mmtile<128>(As, Bs, r0, c0, v);

    float4 bb0 = __ldg((const float4*)(bias + c0));
    float4 bb1 = __ldg((const float4*)(bias + c0 + 4));
    float bcol[8] = {bb0.x, bb0.y, bb0.z, bb0.w, bb1.x, bb1.y, bb1.z, bb1.w};
    #pragma unroll
    for (int r = 0; r < 8; r++) {
        float ss = 0.f;
        #pragma unroll
        for (int c = 0; c < 8; c++) {
            float t = tanhf(v[r][c] + bcol[c]);
            v[r][c] = t; ss += t * t;
        }
        #pragma unroll
        for (int o = 8; o; o >>= 1) ss += __shfl_xor_sync(0xffffffffu, ss, o);
        float inv = 1.f / fmaxf(sqrtf(ss), 1e-12f);
        #pragma unroll
        for (int c = 0; c < 8; c++) v[r][c] *= inv;
        int grow = row0 + r0 + r;
        if (grow < NN) {
            *(float4*)&g_x[(size_t)grow * 128 + c0] =
                make_float4(v[r][0], v[r][1], v[r][2], v[r][3]);
            *(float4*)&g_x[(size_t)grow * 128 + c0 + 4] =
                make_float4(v[r][4], v[r][5], v[r][6], v[r][7]);
        }
    }
    __syncthreads();

    #pragma unroll
    for (int r = 0; r < 8; r++) {
        *(float4*)&As[(r0 + r) * 128 + c0] =
            make_float4(v[r][0], v[r][1], v[r][2], v[r][3]);
        *(float4*)&As[(r0 + r) * 128 + c0 + 4] =
            make_float4(v[r][4], v[r][5], v[r][6], v[r][7]);
    }
    for (int i = tid; i < 128 * 32; i += 256) {
        int kk = i >> 5, c4 = i & 31;
        float4 w = __ldg((const float4*)Wg + kk * 32 + c4);
        *(float4*)&Bs[kk * 128 + c4 * 4] = w;
    }
    __syncthreads();

    mmtile<128>(As, Bs, r0, c0, v);
    #pragma unroll
    for (int r = 0; r < 8; r++) {
        int grow = row0 + r0 + r;
        if (grow < NN) {
            *(float4*)&g_xw[(size_t)grow * 128 + c0] =
                make_float4(v[r][0], v[r][1], v[r][2], v[r][3]);
            *(float4*)&g_xw[(size_t)grow * 128 + c0 + 4] =
                make_float4(v[r][4], v[r][5], v[r][6], v[r][7]);
        }
    }
}

// ---------------- rep = lrelu(h@Wg1.T+bg1 + lrelu(x@Wl1.T+bl1) + id_emb) ----------------
__global__ void __launch_bounds__(256, 1) k_rep(
    const float* __restrict__ Wl1, const float* __restrict__ bl1,
    const float* __restrict__ Wg1, const float* __restrict__ bg1,
    const float* __restrict__ id_emb, float* __restrict__ rep)
{
    extern __shared__ float smx[];
    float* Xs  = smx;            // 128 x 128
    float* Hs  = smx + 16384;    // 128 x 128
    float* W1s = smx + 32768;    // 128 x 64, later epilogue buf
    float* Wgs = smx + 40960;    // 128 x 64
    const int row0 = blockIdx.x * 128;
    int rowlim = NN - row0; if (rowlim > 128) rowlim = 128;
    const int tid = threadIdx.x;

    for (int i = tid; i < 128 * 32; i += 256) {
        int r = i >> 5, c4 = i & 31;
        float4 vx = make_float4(0.f, 0.f, 0.f, 0.f), vh = vx;
        if (r < rowlim) {
            vx = *((const float4*)(g_x + (size_t)(row0 + r) * 128) + c4);
            vh = *((const float4*)(g_h + (size_t)(row0 + r) * 128) + c4);
        }
        *(float4*)&Xs[r * 128 + c4 * 4] = vx;
        *(float4*)&Hs[r * 128 + c4 * 4] = vh;
    }
    for (int i = tid; i < 64 * 32; i += 256) {
        int j = i & 63, c4 = i >> 6;
        float4 v1 = __ldg((const float4*)Wl1 + j * 32 + c4);
        float4 vg = __ldg((const float4*)Wg1 + j * 32 + c4);
        W1s[(c4 * 4 + 0) * 64 + j] = v1.x; W1s[(c4 * 4 + 1) * 64 + j] = v1.y;
        W1s[(c4 * 4 + 2) * 64 + j] = v1.z; W1s[(c4 * 4 + 3) * 64 + j] = v1.w;
        Wgs[(c4 * 4 + 0) * 64 + j] = vg.x; Wgs[(c4 * 4 + 1) * 64 + j] = vg.y;
        Wgs[(c4 * 4 + 2) * 64 + j] = vg.z; Wgs[(c4 * 4 + 3) * 64 + j] = vg.w;
    }
    __syncthreads();

    const int half = tid >> 7, t = tid & 127;
    const int r0 = (t >> 3) * 8, c0 = (t & 7) * 8;
    const float* Ablk = half ? Hs : Xs;
    const float* Wblk = half ? Wgs : W1s;
    float v[8][8];
    mmtile<64>(Ablk, Wblk, r0, c0, v);
    __syncthreads();

    float* buf = W1s;
    if (half == 0) {
        float4 b0 = __ldg((const float4*)(bl1 + c0));
        float4 b1 = __ldg((const float4*)(bl1 + c0 + 4));
        float bc[8] = {b0.x, b0.y, b0.z, b0.w, b1.x, b1.y, b1.z, b1.w};
        #pragma unroll
        for (int r = 0; r < 8; r++) {
            int grow = row0 + r0 + r;
            float4 e0 = make_float4(0.f, 0.f, 0.f, 0.f), e1 = e0;
            if (grow < NN) {
                e0 = __ldg((const float4*)(id_emb + (size_t)grow * 64 + c0));
                e1 = __ldg((const float4*)(id_emb + (size_t)grow * 64 + c0 + 4));
            }
            float em[8] = {e0.x, e0.y, e0.z, e0.w, e1.x, e1.y, e1.z, e1.w};
            #pragma unroll
            for (int c = 0; c < 8; c++)
                buf[(r0 + r) * 64 + c0 + c] = lrelu(v[r][c] + bc[c]) + em[c];
        }
    }
    __syncthreads();
    if (half == 1) {
        float4 b0 = __ldg((const float4*)(bg1 + c0));
        float4 b1 = __ldg((const float4*)(bg1 + c0 + 4));
        float bc[8] = {b0.x, b0.y, b0.z, b0.w, b1.x, b1.y, b1.z, b1.w};
        #pragma unroll
        for (int r = 0; r < 8; r++) {
            int grow = row0 + r0 + r;
            if (grow < NN) {
                float o[8];
                #pragma unroll
                for (int c = 0; c < 8; c++)
                    o[c] = lrelu(v[r][c] + bc[c] + buf[(r0 + r) * 64 + c0 + c]);
                *(float4*)&rep[(size_t)grow * 64 + c0] =
                    make_float4(o[0], o[1], o[2], o[3]);
                *(float4*)&rep[(size_t)grow * 64 + c0 + 4] =
                    make_float4(o[4], o[5], o[6], o[7]);
            }
        }
    }
}

// ---------------- batch head ----------------
__global__ void k_batch(const float* __restrict__ rep,
                        const int* __restrict__ un, const int* __restrict__ pit,
                        const int* __restrict__ nit,
                        const float* __restrict__ Wp1, const float* __restrict__ bp1,
                        const float* __restrict__ Wp2, const float* __restrict__ bp2,
                        float* __restrict__ out_pos, float* __restrict__ out_neg,
                        float* __restrict__ out_pred)
{
    int gt = blockIdx.x * 256 + threadIdx.x;
    int w = gt >> 5, lane = gt & 31;
    if (w >= NB) return;
    int iu = __ldg(un + w), ip = __ldg(pit + w), inn = __ldg(nit + w);
    float u0 = __ldg(rep + (size_t)iu * DX + lane), u1 = __ldg(rep + (size_t)iu * DX + 32 + lane);
    float p0 = __ldg(rep + (size_t)ip * DX + lane), p1 = __ldg(rep + (size_t)ip * DX + 32 + lane);
    float n0 = __ldg(rep + (size_t)inn * DX + lane), n1 = __ldg(rep + (size_t)inn * DX + 32 + lane);
    float ps = u0 * p0 + u1 * p1;
    float ns = u0 * n0 + u1 * n1;
    #pragma unroll
    for (int o = 16; o; o >>= 1) {
        ps += __shfl_xor_sync(0xffffffffu, ps, o);
        ns += __shfl_xor_sync(0xffffffffu, ns, o);
    }
    float h0 = __ldg(bp1 + lane), h1 = __ldg(bp1 + lane + 32);
    #pragma unroll 4
    for (int k = 0; k < 128; k++) {
        float srcv = (k < 32) ? u0 : (k < 64) ? u1 : (k < 96) ? p0 : p1;
        float v = __shfl_sync(0xffffffffu, srcv, k & 31);
        h0 += __ldg(Wp1 + lane * 128 + k) * v;
        h1 += __ldg(Wp1 + (lane + 32) * 128 + k) * v;
    }
    h0 = lrelu(h0); h1 = lrelu(h1);
    float pp = __ldg(Wp2 + lane) * h0 + __ldg(Wp2 + lane + 32) * h1;
    #pragma unroll
    for (int o = 16; o; o >>= 1) pp += __shfl_xor_sync(0xffffffffu, pp, o);
    if (lane == 0) {
        out_pos[w] = ps;
        out_neg[w] = ns;
        out_pred[w] = 1.f / (1.f + __expf(-(pp + __ldg(bp2))));
    }
}

// ---------------- launch ----------------
extern "C" void kernel_launch(void* const* d_in, const int* in_sizes, int n_in,
                              void* d_out, int out_size)
{
    const float* feat   = (const float*)d_in[0];
    const float* ufeat  = (const float*)d_in[1];
    const float* Wm     = (const float*)d_in[2];
    const float* bm     = (const float*)d_in[3];
    const float* Wu     = (const float*)d_in[4];
    const float* bu     = (const float*)d_in[5];
    const float* Wgat   = (const float*)d_in[6];
    const float* bgat   = (const float*)d_in[7];
    const float* Wl1    = (const float*)d_in[8];
    const float* bl1    = (const float*)d_in[9];
    const float* Wg1    = (const float*)d_in[10];
    const float* bg1    = (const float*)d_in[11];
    const float* id_emb = (const float*)d_in[12];
    const float* Wp1    = (const float*)d_in[13];
    const float* bp1    = (const float*)d_in[14];
    const float* Wp2    = (const float*)d_in[15];
    const float* bp2    = (const float*)d_in[16];
    const int*   ei     = (const int*)d_in[17];
    const int*   un     = (const int*)d_in[18];
    const int*   pit    = (const int*)d_in[19];
    const int*   nit    = (const int*)d_in[20];

    float* out      = (float*)d_out;
    float* out_pos  = out;
    float* out_neg  = out + NB;
    float* rep      = out + 2 * NB;
    float* out_pred = out + 2 * NB + (size_t)NN * DX;

    // lazy one-time init (first call is the uncaptured correctness run)
    static cudaStream_t s_side = nullptr;
    static cudaEvent_t ev_fork = nullptr, ev_join = nullptr;
    if (!s_side) {
        cudaStreamCreateWithFlags(&s_side, cudaStreamNonBlocking);
        cudaEventCreateWithFlags(&ev_fork, cudaEventDisableTiming);
        cudaEventCreateWithFlags(&ev_join, cudaEventDisableTiming);
        cudaFuncSetAttribute(k_gemm_fused, cudaFuncAttributeMaxDynamicSharedMemorySize, 131072);
        cudaFuncSetAttribute(k_rep,        cudaFuncAttributeMaxDynamicSharedMemorySize, 196608);
    }

    // fork: CSR build chain on side stream, GEMM on main stream (independent)
    cudaEventRecord(ev_fork, 0);
    cudaStreamWaitEvent(s_side, ev_fork, 0);

    k_zero <<<(NN + 255) / 256, 256, 0, s_side>>>();
    k_hist <<<(NE + 255) / 256, 256, 0, s_side>>>(ei);
    k_scan <<<1, 1024, 0, s_side>>>();
    k_build<<<(NE + 255) / 256, 256, 0, s_side>>>(ei);

    k_gemm_fused<<<782, 256, 131072>>>(feat, ufeat, Wm, bm, Wu, bu, Wgat);

    // join: aggregation needs both CSR and xw
    cudaEventRecord(ev_join, s_side);
    cudaStreamWaitEvent(0, ev_join, 0);

    k_aggr<<<(NN * 32 + 255) / 256, 256>>>(bgat);
    k_rep<<<782, 256, 196608>>>(Wl1, bl1, Wg1, bg1, id_emb, rep);
    k_batch<<<NB / 8, 256>>>(rep, un, pit, nit, Wp1, bp1, Wp2, bp2,
                             out_pos, out_neg, out_pred);
}

// round 7
// speedup vs baseline: 1.1548x; 1.0503x over previous
#include <cuda_runtime.h>
#include <math.h>

#define NN     100000
#define NITEM  80000
#define DD     128
#define DX     64
#define NE     800000
#define NB     4096
#define NSPLIT 50048          // = 391 * 128, node/row split for aggr/rep pipeline
#define RBLK0  391            // rep blocks in first half
#define RBLK1  391            // rep blocks in second half (covers to 100096, guarded)

// ---------------- device scratch ----------------
__device__ __align__(16) float g_x [(size_t)NN * DD];
__device__ __align__(16) float g_xw[(size_t)NN * DD];
__device__ __align__(16) float g_h [(size_t)NN * DD];   // finalized gat output
__device__ int g_deg[NN];        // out-degree of src
__device__ int g_cnt[NN];        // in-degree of dst (histogram)
__device__ int g_cur[NN];        // build cursors
__device__ int g_off[NN + 1];    // CSR offsets by dst
__device__ int g_csr_src[NE];    // src ids grouped by dst

__device__ __forceinline__ float lrelu(float v) { return v > 0.f ? v : 0.01f * v; }

// ---------------- packed f32x2 helpers (Blackwell FFMA2) ----------------
__device__ __forceinline__ unsigned long long dup2(float a) {
    unsigned long long r;
    asm("mov.b64 %0, {%1, %1};" : "=l"(r) : "r"(__float_as_uint(a)));
    return r;
}
__device__ __forceinline__ void fma2(unsigned long long& d, unsigned long long a,
                                     unsigned long long b) {
    asm("fma.rn.f32x2 %0, %1, %2, %0;" : "+l"(d) : "l"(a), "l"(b));
}
__device__ __forceinline__ float lo32(unsigned long long v) {
    return __uint_as_float((unsigned)v);
}
__device__ __forceinline__ float hi32(unsigned long long v) {
    return __uint_as_float((unsigned)(v >> 32));
}

template <int LDB>
__device__ __forceinline__ void mmtile(const float* __restrict__ As,
                                       const float* __restrict__ Bs,
                                       int r0, int c0, float (&out)[8][8]) {
    unsigned long long acc[8][4];
    #pragma unroll
    for (int r = 0; r < 8; r++) {
        acc[r][0] = 0ull; acc[r][1] = 0ull; acc[r][2] = 0ull; acc[r][3] = 0ull;
    }
    #pragma unroll 1
    for (int k = 0; k < 128; k += 4) {
        float4 av[8];
        #pragma unroll
        for (int r = 0; r < 8; r++)
            av[r] = *(const float4*)(As + (r0 + r) * 128 + k);
        #pragma unroll
        for (int kk = 0; kk < 4; kk++) {
            ulonglong2 b01 = *(const ulonglong2*)(Bs + (k + kk) * LDB + c0);
            ulonglong2 b23 = *(const ulonglong2*)(Bs + (k + kk) * LDB + c0 + 4);
            #pragma unroll
            for (int r = 0; r < 8; r++) {
                float a = (kk == 0) ? av[r].x : (kk == 1) ? av[r].y
                        : (kk == 2) ? av[r].z : av[r].w;
                unsigned long long ad = dup2(a);
                fma2(acc[r][0], ad, b01.x);
                fma2(acc[r][1], ad, b01.y);
                fma2(acc[r][2], ad, b23.x);
                fma2(acc[r][3], ad, b23.y);
            }
        }
    }
    #pragma unroll
    for (int r = 0; r < 8; r++) {
        out[r][0] = lo32(acc[r][0]); out[r][1] = hi32(acc[r][0]);
        out[r][2] = lo32(acc[r][1]); out[r][3] = hi32(acc[r][1]);
        out[r][4] = lo32(acc[r][2]); out[r][5] = hi32(acc[r][2]);
        out[r][6] = lo32(acc[r][3]); out[r][7] = hi32(acc[r][3]);
    }
}

// ---------------- zero counters ----------------
__global__ void k_zero() {
    int i = blockIdx.x * 256 + threadIdx.x;
    if (i < NN) { g_deg[i] = 0; g_cnt[i] = 0; g_cur[i] = 0; }
}

// ---------------- histogram: src out-degree + dst in-degree ----------------
__global__ void k_hist(const int* __restrict__ ei) {
    int e = blockIdx.x * 256 + threadIdx.x;
    if (e < NE) {
        atomicAdd(&g_deg[__ldg(ei + e)], 1);
        atomicAdd(&g_cnt[__ldg(ei + NE + e)], 1);
    }
}

// ---------------- exclusive scan of g_cnt -> g_off (single block) ----------------
__global__ void __launch_bounds__(1024) k_scan() {
    __shared__ int part[1024];
    const int t = threadIdx.x;
    const int per = (NN + 1023) / 1024;
    int s0 = t * per, s1 = s0 + per; if (s1 > NN) s1 = NN;
    int s = 0;
    for (int i = s0; i < s1; i++) s += g_cnt[i];
    part[t] = s;
    __syncthreads();
    #pragma unroll
    for (int off = 1; off < 1024; off <<= 1) {
        int v = (t >= off) ? part[t - off] : 0;
        __syncthreads();
        part[t] += v;
        __syncthreads();
    }
    int base = (t == 0) ? 0 : part[t - 1];
    for (int i = s0; i < s1; i++) { g_off[i] = base; base += g_cnt[i]; }
    if (t == 1023) g_off[NN] = base;
}

// ---------------- CSR build: group src ids by dst ----------------
__global__ void k_build(const int* __restrict__ ei) {
    int e = blockIdx.x * 256 + threadIdx.x;
    if (e >= NE) return;
    int sj = __ldg(ei + e);
    int di = __ldg(ei + NE + e);
    int pos = g_off[di] + atomicAdd(&g_cur[di], 1);
    g_csr_src[pos] = sj;
}

// ---------------- fused GAT aggregation over node range [base, base+count) ----------
// h[d] = lrelu(l2norm( (sum_e ev_e * xw[src_e]) / (sum_e ev_e + 1e-16) + bgat ))
__global__ void __launch_bounds__(256) k_aggr(const float* __restrict__ bgat,
                                              int base, int count) {
    int gt = blockIdx.x * 256 + threadIdx.x;
    int wi = gt >> 5, lane = gt & 31;
    if (wi >= count) return;
    int w = base + wi;

    float4 xd = *((const float4*)(g_xw + (size_t)w * DD) + lane);
    int p   = __ldg(&g_off[w]);
    int end = __ldg(&g_off[w + 1]);

    float4 acc = make_float4(0.f, 0.f, 0.f, 0.f);
    float s = 0.f;

    float4 a; float dg;
    if (p < end) {
        int sj = __ldg(&g_csr_src[p]);
        a  = *((const float4*)(g_xw + (size_t)sj * DD) + lane);
        dg = (float)__ldg(&g_deg[sj]);
    }
    while (p < end) {
        float4 a_n; float dg_n;
        if (p + 1 < end) {
            int sj = __ldg(&g_csr_src[p + 1]);
            a_n  = *((const float4*)(g_xw + (size_t)sj * DD) + lane);
            dg_n = (float)__ldg(&g_deg[sj]);
        }
        float d = a.x * xd.x + a.y * xd.y + a.z * xd.z + a.w * xd.w;
        #pragma unroll
        for (int o = 16; o; o >>= 1) d += __shfl_xor_sync(0xffffffffu, d, o);
        float gate = 1.f / (1.f + __expf(-rsqrtf(dg) * d));
        float ev = __expf(d * gate);
        s += ev;
        acc.x += ev * a.x; acc.y += ev * a.y;
        acc.z += ev * a.z; acc.w += ev * a.w;
        a = a_n; dg = dg_n; p++;
    }

    float inv_s = 1.f / (s + 1e-16f);
    float4 bb = __ldg((const float4*)bgat + lane);
    float4 h = make_float4(acc.x * inv_s + bb.x, acc.y * inv_s + bb.y,
                           acc.z * inv_s + bb.z, acc.w * inv_s + bb.w);
    float ss = h.x * h.x + h.y * h.y + h.z * h.z + h.w * h.w;
    #pragma unroll
    for (int o = 16; o; o >>= 1) ss += __shfl_xor_sync(0xffffffffu, ss, o);
    float inv = 1.f / fmaxf(sqrtf(ss), 1e-12f);
    h.x = lrelu(h.x * inv); h.y = lrelu(h.y * inv);
    h.z = lrelu(h.z * inv); h.w = lrelu(h.w * inv);
    *((float4*)(g_h + (size_t)w * DD) + lane) = h;
}

// ---------------- fused: x = l2norm(tanh(feat@W.T+b)); xw = x@W_gat ----------------
__global__ void __launch_bounds__(256, 1) k_gemm_fused(
    const float* __restrict__ feat, const float* __restrict__ ufeat,
    const float* __restrict__ Wm, const float* __restrict__ bm,
    const float* __restrict__ Wu, const float* __restrict__ bu,
    const float* __restrict__ Wg)
{
    extern __shared__ float smx[];
    float* As = smx;            // 128 x 128
    float* Bs = smx + 16384;    // 128 x 128
    const int row0 = blockIdx.x * 128;
    const bool user = row0 >= NITEM;
    const float* A    = user ? (ufeat + (size_t)(row0 - NITEM) * DD)
                             : (feat  + (size_t)row0 * DD);
    const float* W    = user ? Wu : Wm;
    const float* bias = user ? bu : bm;
    int rowlim = NN - row0; if (rowlim > 128) rowlim = 128;
    const int tid = threadIdx.x;

    for (int i = tid; i < 128 * 32; i += 256) {
        int r = i >> 5, c4 = i & 31;
        float4 v = make_float4(0.f, 0.f, 0.f, 0.f);
        if (r < rowlim) v = __ldg((const float4*)A + (size_t)r * 32 + c4);
        *(float4*)&As[r * 128 + c4 * 4] = v;
    }
    for (int i = tid; i < 128 * 32; i += 256) {
        int j = i & 127, c4 = i >> 7;
        float4 v = __ldg((const float4*)W + j * 32 + c4);
        Bs[(c4 * 4 + 0) * 128 + j] = v.x;
        Bs[(c4 * 4 + 1) * 128 + j] = v.y;
        Bs[(c4 * 4 + 2) * 128 + j] = v.z;
        Bs[(c4 * 4 + 3) * 128 + j] = v.w;
    }
    __syncthreads();

    const int ty = tid >> 4, tx = tid & 15;
    const int r0 = ty * 8, c0 = tx * 8;
    float v[8][8];
    mmtile<128>(As, Bs, r0, c0, v);

    float4 bb0 = __ldg((const float4*)(bias + c0));
    float4 bb1 = __ldg((const float4*)(bias + c0 + 4));
    float bcol[8] = {bb0.x, bb0.y, bb0.z, bb0.w, bb1.x, bb1.y, bb1.z, bb1.w};
    #pragma unroll
    for (int r = 0; r < 8; r++) {
        float ss = 0.f;
        #pragma unroll
        for (int c = 0; c < 8; c++) {
            float t = tanhf(v[r][c] + bcol[c]);
            v[r][c] = t; ss += t * t;
        }
        #pragma unroll
        for (int o = 8; o; o >>= 1) ss += __shfl_xor_sync(0xffffffffu, ss, o);
        float inv = 1.f / fmaxf(sqrtf(ss), 1e-12f);
        #pragma unroll
        for (int c = 0; c < 8; c++) v[r][c] *= inv;
        int grow = row0 + r0 + r;
        if (grow < NN) {
            *(float4*)&g_x[(size_t)grow * 128 + c0] =
                make_float4(v[r][0], v[r][1], v[r][2], v[r][3]);
            *(float4*)&g_x[(size_t)grow * 128 + c0 + 4] =
                make_float4(v[r][4], v[r][5], v[r][6], v[r][7]);
        }
    }
    __syncthreads();

    #pragma unroll
    for (int r = 0; r < 8; r++) {
        *(float4*)&As[(r0 + r) * 128 + c0] =
            make_float4(v[r][0], v[r][1], v[r][2], v[r][3]);
        *(float4*)&As[(r0 + r) * 128 + c0 + 4] =
            make_float4(v[r][4], v[r][5], v[r][6], v[r][7]);
    }
    for (int i = tid; i < 128 * 32; i += 256) {
        int kk = i >> 5, c4 = i & 31;
        float4 w = __ldg((const float4*)Wg + kk * 32 + c4);
        *(float4*)&Bs[kk * 128 + c4 * 4] = w;
    }
    __syncthreads();

    mmtile<128>(As, Bs, r0, c0, v);
    #pragma unroll
    for (int r = 0; r < 8; r++) {
        int grow = row0 + r0 + r;
        if (grow < NN) {
            *(float4*)&g_xw[(size_t)grow * 128 + c0] =
                make_float4(v[r][0], v[r][1], v[r][2], v[r][3]);
            *(float4*)&g_xw[(size_t)grow * 128 + c0 + 4] =
                make_float4(v[r][4], v[r][5], v[r][6], v[r][7]);
        }
    }
}

// ---------------- rep = lrelu(h@Wg1.T+bg1 + lrelu(x@Wl1.T+bl1) + id_emb) ----------------
__global__ void __launch_bounds__(256, 1) k_rep(
    const float* __restrict__ Wl1, const float* __restrict__ bl1,
    const float* __restrict__ Wg1, const float* __restrict__ bg1,
    const float* __restrict__ id_emb, float* __restrict__ rep, int blk0)
{
    extern __shared__ float smx[];
    float* Xs  = smx;            // 128 x 128
    float* Hs  = smx + 16384;    // 128 x 128
    float* W1s = smx + 32768;    // 128 x 64, later epilogue buf
    float* Wgs = smx + 40960;    // 128 x 64
    const int row0 = (blockIdx.x + blk0) * 128;
    int rowlim = NN - row0; if (rowlim > 128) rowlim = 128;
    const int tid = threadIdx.x;

    for (int i = tid; i < 128 * 32; i += 256) {
        int r = i >> 5, c4 = i & 31;
        float4 vx = make_float4(0.f, 0.f, 0.f, 0.f), vh = vx;
        if (r < rowlim) {
            vx = *((const float4*)(g_x + (size_t)(row0 + r) * 128) + c4);
            vh = *((const float4*)(g_h + (size_t)(row0 + r) * 128) + c4);
        }
        *(float4*)&Xs[r * 128 + c4 * 4] = vx;
        *(float4*)&Hs[r * 128 + c4 * 4] = vh;
    }
    for (int i = tid; i < 64 * 32; i += 256) {
        int j = i & 63, c4 = i >> 6;
        float4 v1 = __ldg((const float4*)Wl1 + j * 32 + c4);
        float4 vg = __ldg((const float4*)Wg1 + j * 32 + c4);
        W1s[(c4 * 4 + 0) * 64 + j] = v1.x; W1s[(c4 * 4 + 1) * 64 + j] = v1.y;
        W1s[(c4 * 4 + 2) * 64 + j] = v1.z; W1s[(c4 * 4 + 3) * 64 + j] = v1.w;
        Wgs[(c4 * 4 + 0) * 64 + j] = vg.x; Wgs[(c4 * 4 + 1) * 64 + j] = vg.y;
        Wgs[(c4 * 4 + 2) * 64 + j] = vg.z; Wgs[(c4 * 4 + 3) * 64 + j] = vg.w;
    }
    __syncthreads();

    const int half = tid >> 7, t = tid & 127;
    const int r0 = (t >> 3) * 8, c0 = (t & 7) * 8;
    const float* Ablk = half ? Hs : Xs;
    const float* Wblk = half ? Wgs : W1s;
    float v[8][8];
    mmtile<64>(Ablk, Wblk, r0, c0, v);
    __syncthreads();

    float* buf = W1s;
    if (half == 0) {
        float4 b0 = __ldg((const float4*)(bl1 + c0));
        float4 b1 = __ldg((const float4*)(bl1 + c0 + 4));
        float bc[8] = {b0.x, b0.y, b0.z, b0.w, b1.x, b1.y, b1.z, b1.w};
        #pragma unroll
        for (int r = 0; r < 8; r++) {
            int grow = row0 + r0 + r;
            float4 e0 = make_float4(0.f, 0.f, 0.f, 0.f), e1 = e0;
            if (grow < NN) {
                e0 = __ldg((const float4*)(id_emb + (size_t)grow * 64 + c0));
                e1 = __ldg((const float4*)(id_emb + (size_t)grow * 64 + c0 + 4));
            }
            float em[8] = {e0.x, e0.y, e0.z, e0.w, e1.x, e1.y, e1.z, e1.w};
            #pragma unroll
            for (int c = 0; c < 8; c++)
                buf[(r0 + r) * 64 + c0 + c] = lrelu(v[r][c] + bc[c]) + em[c];
        }
    }
    __syncthreads();
    if (half == 1) {
        float4 b0 = __ldg((const float4*)(bg1 + c0));
        float4 b1 = __ldg((const float4*)(bg1 + c0 + 4));
        float bc[8] = {b0.x, b0.y, b0.z, b0.w, b1.x, b1.y, b1.z, b1.w};
        #pragma unroll
        for (int r = 0; r < 8; r++) {
            int grow = row0 + r0 + r;
            if (grow < NN) {
                float o[8];
                #pragma unroll
                for (int c = 0; c < 8; c++)
                    o[c] = lrelu(v[r][c] + bc[c] + buf[(r0 + r) * 64 + c0 + c]);
                *(float4*)&rep[(size_t)grow * 64 + c0] =
                    make_float4(o[0], o[1], o[2], o[3]);
                *(float4*)&rep[(size_t)grow * 64 + c0 + 4] =
                    make_float4(o[4], o[5], o[6], o[7]);
            }
        }
    }
}

// ---------------- batch head ----------------
__global__ void k_batch(const float* __restrict__ rep,
                        const int* __restrict__ un, const int* __restrict__ pit,
                        const int* __restrict__ nit,
                        const float* __restrict__ Wp1, const float* __restrict__ bp1,
                        const float* __restrict__ Wp2, const float* __restrict__ bp2,
                        float* __restrict__ out_pos, float* __restrict__ out_neg,
                        float* __restrict__ out_pred)
{
    int gt = blockIdx.x * 256 + threadIdx.x;
    int w = gt >> 5, lane = gt & 31;
    if (w >= NB) return;
    int iu = __ldg(un + w), ip = __ldg(pit + w), inn = __ldg(nit + w);
    float u0 = __ldg(rep + (size_t)iu * DX + lane), u1 = __ldg(rep + (size_t)iu * DX + 32 + lane);
    float p0 = __ldg(rep + (size_t)ip * DX + lane), p1 = __ldg(rep + (size_t)ip * DX + 32 + lane);
    float n0 = __ldg(rep + (size_t)inn * DX + lane), n1 = __ldg(rep + (size_t)inn * DX + 32 + lane);
    float ps = u0 * p0 + u1 * p1;
    float ns = u0 * n0 + u1 * n1;
    #pragma unroll
    for (int o = 16; o; o >>= 1) {
        ps += __shfl_xor_sync(0xffffffffu, ps, o);
        ns += __shfl_xor_sync(0xffffffffu, ns, o);
    }
    float h0 = __ldg(bp1 + lane), h1 = __ldg(bp1 + lane + 32);
    #pragma unroll 4
    for (int k = 0; k < 128; k++) {
        float srcv = (k < 32) ? u0 : (k < 64) ? u1 : (k < 96) ? p0 : p1;
        float v = __shfl_sync(0xffffffffu, srcv, k & 31);
        h0 += __ldg(Wp1 + lane * 128 + k) * v;
        h1 += __ldg(Wp1 + (lane + 32) * 128 + k) * v;
    }
    h0 = lrelu(h0); h1 = lrelu(h1);
    float pp = __ldg(Wp2 + lane) * h0 + __ldg(Wp2 + lane + 32) * h1;
    #pragma unroll
    for (int o = 16; o; o >>= 1) pp += __shfl_xor_sync(0xffffffffu, pp, o);
    if (lane == 0) {
        out_pos[w] = ps;
        out_neg[w] = ns;
        out_pred[w] = 1.f / (1.f + __expf(-(pp + __ldg(bp2))));
    }
}

// ---------------- launch ----------------
extern "C" void kernel_launch(void* const* d_in, const int* in_sizes, int n_in,
                              void* d_out, int out_size)
{
    const float* feat   = (const float*)d_in[0];
    const float* ufeat  = (const float*)d_in[1];
    const float* Wm     = (const float*)d_in[2];
    const float* bm     = (const float*)d_in[3];
    const float* Wu     = (const float*)d_in[4];
    const float* bu     = (const float*)d_in[5];
    const float* Wgat   = (const float*)d_in[6];
    const float* bgat   = (const float*)d_in[7];
    const float* Wl1    = (const float*)d_in[8];
    const float* bl1    = (const float*)d_in[9];
    const float* Wg1    = (const float*)d_in[10];
    const float* bg1    = (const float*)d_in[11];
    const float* id_emb = (const float*)d_in[12];
    const float* Wp1    = (const float*)d_in[13];
    const float* bp1    = (const float*)d_in[14];
    const float* Wp2    = (const float*)d_in[15];
    const float* bp2    = (const float*)d_in[16];
    const int*   ei     = (const int*)d_in[17];
    const int*   un     = (const int*)d_in[18];
    const int*   pit    = (const int*)d_in[19];
    const int*   nit    = (const int*)d_in[20];

    float* out      = (float*)d_out;
    float* out_pos  = out;
    float* out_neg  = out + NB;
    float* rep      = out + 2 * NB;
    float* out_pred = out + 2 * NB + (size_t)NN * DX;

    // lazy one-time init (first call is the uncaptured correctness run)
    static cudaStream_t s_side = nullptr;
    static cudaEvent_t ev_fork = nullptr, ev_join = nullptr, ev_a0 = nullptr, ev_a1 = nullptr;
    if (!s_side) {
        cudaStreamCreateWithFlags(&s_side, cudaStreamNonBlocking);
        cudaEventCreateWithFlags(&ev_fork, cudaEventDisableTiming);
        cudaEventCreateWithFlags(&ev_join, cudaEventDisableTiming);
        cudaEventCreateWithFlags(&ev_a0,   cudaEventDisableTiming);
        cudaEventCreateWithFlags(&ev_a1,   cudaEventDisableTiming);
        cudaFuncSetAttribute(k_gemm_fused, cudaFuncAttributeMaxDynamicSharedMemorySize, 131072);
        cudaFuncSetAttribute(k_rep,        cudaFuncAttributeMaxDynamicSharedMemorySize, 196608);
    }

    // fork: CSR build chain on side stream, GEMM on main stream (independent)
    cudaEventRecord(ev_fork, 0);
    cudaStreamWaitEvent(s_side, ev_fork, 0);

    k_zero <<<(NN + 255) / 256, 256, 0, s_side>>>();
    k_hist <<<(NE + 255) / 256, 256, 0, s_side>>>(ei);
    k_scan <<<1, 1024, 0, s_side>>>();
    k_build<<<(NE + 255) / 256, 256, 0, s_side>>>(ei);

    k_gemm_fused<<<782, 256, 131072>>>(feat, ufeat, Wm, bm, Wu, bu, Wgat);

    // join: aggregation needs both CSR and xw
    cudaEventRecord(ev_join, s_side);
    cudaStreamWaitEvent(0, ev_join, 0);

    // pipeline: aggr half0 -> { rep half0 (main) || aggr half1 (side) } -> rep half1
    k_aggr<<<(NSPLIT * 32 + 255) / 256, 256>>>(bgat, 0, NSPLIT);
    cudaEventRecord(ev_a0, 0);
    cudaStreamWaitEvent(s_side, ev_a0, 0);
    k_aggr<<<((NN - NSPLIT) * 32 + 255) / 256, 256, 0, s_side>>>(bgat, NSPLIT, NN - NSPLIT);
    cudaEventRecord(ev_a1, s_side);

    k_rep<<<RBLK0, 256, 196608>>>(Wl1, bl1, Wg1, bg1, id_emb, rep, 0);
    cudaStreamWaitEvent(0, ev_a1, 0);
    k_rep<<<RBLK1, 256, 196608>>>(Wl1, bl1, Wg1, bg1, id_emb, rep, RBLK0);

    k_batch<<<NB / 8, 256>>>(rep, un, pit, nit, Wp1, bp1, Wp2, bp2,
                             out_pos, out_neg, out_pred);
}

// round 8
// speedup vs baseline: 1.3087x; 1.1333x over previous
#include <cuda_runtime.h>
#include <math.h>

#define NN     100000
#define NITEM  80000
#define DD     128
#define DX     64
#define NE     800000
#define NB     4096
#define NSPLIT 50048          // = 391 * 128, node/row split for aggr/rep pipeline
#define RBLK0  391
#define RBLK1  391

// ---------------- device scratch ----------------
__device__ __align__(16) float g_x [(size_t)NN * DD];
__device__ __align__(16) float g_xw[(size_t)NN * DD];
__device__ __align__(16) float g_h [(size_t)NN * DD];
__device__ int g_deg[NN];
__device__ int g_cnt[NN];
__device__ int g_cur[NN];
__device__ int g_off[NN + 1];
__device__ int g_csr_src[NE];

__device__ __forceinline__ float lrelu(float v) { return v > 0.f ? v : 0.01f * v; }

// ---------------- packed f32x2 helpers (Blackwell FFMA2) ----------------
__device__ __forceinline__ unsigned long long dup2(float a) {
    unsigned long long r;
    asm("mov.b64 %0, {%1, %1};" : "=l"(r) : "r"(__float_as_uint(a)));
    return r;
}
__device__ __forceinline__ void fma2(unsigned long long& d, unsigned long long a,
                                     unsigned long long b) {
    asm("fma.rn.f32x2 %0, %1, %2, %0;" : "+l"(d) : "l"(a), "l"(b));
}
__device__ __forceinline__ float lo32(unsigned long long v) {
    return __uint_as_float((unsigned)v);
}
__device__ __forceinline__ float hi32(unsigned long long v) {
    return __uint_as_float((unsigned)(v >> 32));
}

// 8x4 per-thread microtile GEMM over K=128. A stride 128, B stride LDB.
template <int LDB>
__device__ __forceinline__ void mmtile4(const float* __restrict__ As,
                                        const float* __restrict__ Bs,
                                        int r0, int c0, float (&out)[8][4]) {
    unsigned long long acc[8][2];
    #pragma unroll
    for (int r = 0; r < 8; r++) { acc[r][0] = 0ull; acc[r][1] = 0ull; }
    #pragma unroll 1
    for (int k = 0; k < 128; k += 4) {
        float4 av[8];
        #pragma unroll
        for (int r = 0; r < 8; r++)
            av[r] = *(const float4*)(As + (r0 + r) * 128 + k);
        #pragma unroll
        for (int kk = 0; kk < 4; kk++) {
            ulonglong2 b01 = *(const ulonglong2*)(Bs + (k + kk) * LDB + c0);
            #pragma unroll
            for (int r = 0; r < 8; r++) {
                float a = (kk == 0) ? av[r].x : (kk == 1) ? av[r].y
                        : (kk == 2) ? av[r].z : av[r].w;
                unsigned long long ad = dup2(a);
                fma2(acc[r][0], ad, b01.x);
                fma2(acc[r][1], ad, b01.y);
            }
        }
    }
    #pragma unroll
    for (int r = 0; r < 8; r++) {
        out[r][0] = lo32(acc[r][0]); out[r][1] = hi32(acc[r][0]);
        out[r][2] = lo32(acc[r][1]); out[r][3] = hi32(acc[r][1]);
    }
}

// ---------------- zero counters ----------------
__global__ void k_zero() {
    int i = blockIdx.x * 256 + threadIdx.x;
    if (i < NN) { g_deg[i] = 0; g_cnt[i] = 0; g_cur[i] = 0; }
}

// ---------------- histogram ----------------
__global__ void k_hist(const int* __restrict__ ei) {
    int e = blockIdx.x * 256 + threadIdx.x;
    if (e < NE) {
        atomicAdd(&g_deg[__ldg(ei + e)], 1);
        atomicAdd(&g_cnt[__ldg(ei + NE + e)], 1);
    }
}

// ---------------- exclusive scan (single block) ----------------
__global__ void __launch_bounds__(1024) k_scan() {
    __shared__ int part[1024];
    const int t = threadIdx.x;
    const int per = (NN + 1023) / 1024;
    int s0 = t * per, s1 = s0 + per; if (s1 > NN) s1 = NN;
    int s = 0;
    for (int i = s0; i < s1; i++) s += g_cnt[i];
    part[t] = s;
    __syncthreads();
    #pragma unroll
    for (int off = 1; off < 1024; off <<= 1) {
        int v = (t >= off) ? part[t - off] : 0;
        __syncthreads();
        part[t] += v;
        __syncthreads();
    }
    int base = (t == 0) ? 0 : part[t - 1];
    for (int i = s0; i < s1; i++) { g_off[i] = base; base += g_cnt[i]; }
    if (t == 1023) g_off[NN] = base;
}

// ---------------- CSR build ----------------
__global__ void k_build(const int* __restrict__ ei) {
    int e = blockIdx.x * 256 + threadIdx.x;
    if (e >= NE) return;
    int sj = __ldg(ei + e);
    int di = __ldg(ei + NE + e);
    int pos = g_off[di] + atomicAdd(&g_cur[di], 1);
    g_csr_src[pos] = sj;
}

// ---------------- fused GAT aggregation over node range ----------
__global__ void __launch_bounds__(256) k_aggr(const float* __restrict__ bgat,
                                              int base, int count) {
    int gt = blockIdx.x * 256 + threadIdx.x;
    int wi = gt >> 5, lane = gt & 31;
    if (wi >= count) return;
    int w = base + wi;

    float4 xd = *((const float4*)(g_xw + (size_t)w * DD) + lane);
    int p   = __ldg(&g_off[w]);
    int end = __ldg(&g_off[w + 1]);

    float4 acc = make_float4(0.f, 0.f, 0.f, 0.f);
    float s = 0.f;

    float4 a; float dg;
    if (p < end) {
        int sj = __ldg(&g_csr_src[p]);
        a  = *((const float4*)(g_xw + (size_t)sj * DD) + lane);
        dg = (float)__ldg(&g_deg[sj]);
    }
    while (p < end) {
        float4 a_n; float dg_n;
        if (p + 1 < end) {
            int sj = __ldg(&g_csr_src[p + 1]);
            a_n  = *((const float4*)(g_xw + (size_t)sj * DD) + lane);
            dg_n = (float)__ldg(&g_deg[sj]);
        }
        float d = a.x * xd.x + a.y * xd.y + a.z * xd.z + a.w * xd.w;
        #pragma unroll
        for (int o = 16; o; o >>= 1) d += __shfl_xor_sync(0xffffffffu, d, o);
        float gate = 1.f / (1.f + __expf(-rsqrtf(dg) * d));
        float ev = __expf(d * gate);
        s += ev;
        acc.x += ev * a.x; acc.y += ev * a.y;
        acc.z += ev * a.z; acc.w += ev * a.w;
        a = a_n; dg = dg_n; p++;
    }

    float inv_s = 1.f / (s + 1e-16f);
    float4 bb = __ldg((const float4*)bgat + lane);
    float4 h = make_float4(acc.x * inv_s + bb.x, acc.y * inv_s + bb.y,
                           acc.z * inv_s + bb.z, acc.w * inv_s + bb.w);
    float ss = h.x * h.x + h.y * h.y + h.z * h.z + h.w * h.w;
    #pragma unroll
    for (int o = 16; o; o >>= 1) ss += __shfl_xor_sync(0xffffffffu, ss, o);
    float inv = 1.f / fmaxf(sqrtf(ss), 1e-12f);
    h.x = lrelu(h.x * inv); h.y = lrelu(h.y * inv);
    h.z = lrelu(h.z * inv); h.w = lrelu(h.w * inv);
    *((float4*)(g_h + (size_t)w * DD) + lane) = h;
}

// ---------------- fused: x = l2norm(tanh(feat@W.T+b)); xw = x@W_gat ----------------
// 512 threads, 8x4 microtile, 128x128 tile
__global__ void __launch_bounds__(512, 1) k_gemm_fused(
    const float* __restrict__ feat, const float* __restrict__ ufeat,
    const float* __restrict__ Wm, const float* __restrict__ bm,
    const float* __restrict__ Wu, const float* __restrict__ bu,
    const float* __restrict__ Wg)
{
    extern __shared__ float smx[];
    float* As = smx;            // 128 x 128
    float* Bs = smx + 16384;    // 128 x 128
    const int row0 = blockIdx.x * 128;
    const bool user = row0 >= NITEM;
    const float* A    = user ? (ufeat + (size_t)(row0 - NITEM) * DD)
                             : (feat  + (size_t)row0 * DD);
    const float* W    = user ? Wu : Wm;
    const float* bias = user ? bu : bm;
    int rowlim = NN - row0; if (rowlim > 128) rowlim = 128;
    const int tid = threadIdx.x;

    for (int i = tid; i < 128 * 32; i += 512) {
        int r = i >> 5, c4 = i & 31;
        float4 v = make_float4(0.f, 0.f, 0.f, 0.f);
        if (r < rowlim) v = __ldg((const float4*)A + (size_t)r * 32 + c4);
        *(float4*)&As[r * 128 + c4 * 4] = v;
    }
    for (int i = tid; i < 128 * 32; i += 512) {
        int j = i & 127, c4 = i >> 7;
        float4 v = __ldg((const float4*)W + j * 32 + c4);
        Bs[(c4 * 4 + 0) * 128 + j] = v.x;
        Bs[(c4 * 4 + 1) * 128 + j] = v.y;
        Bs[(c4 * 4 + 2) * 128 + j] = v.z;
        Bs[(c4 * 4 + 3) * 128 + j] = v.w;
    }
    __syncthreads();

    // 16 warps x 32 lanes: r0 = warp*8 (broadcast within warp), c0 = lane*4
    const int r0 = (tid >> 5) * 8, c0 = (tid & 31) * 4;
    float v[8][4];
    mmtile4<128>(As, Bs, r0, c0, v);

    float4 bb = __ldg((const float4*)(bias + c0));
    float bcol[4] = {bb.x, bb.y, bb.z, bb.w};
    #pragma unroll
    for (int r = 0; r < 8; r++) {
        float ss = 0.f;
        #pragma unroll
        for (int c = 0; c < 4; c++) {
            float t = tanhf(v[r][c] + bcol[c]);
            v[r][c] = t; ss += t * t;
        }
        #pragma unroll
        for (int o = 16; o; o >>= 1) ss += __shfl_xor_sync(0xffffffffu, ss, o);
        float inv = 1.f / fmaxf(sqrtf(ss), 1e-12f);
        #pragma unroll
        for (int c = 0; c < 4; c++) v[r][c] *= inv;
        int grow = row0 + r0 + r;
        if (grow < NN)
            *(float4*)&g_x[(size_t)grow * 128 + c0] =
                make_float4(v[r][0], v[r][1], v[r][2], v[r][3]);
    }
    __syncthreads();

    // phase 2: As <- x tile, Bs <- W_gat
    #pragma unroll
    for (int r = 0; r < 8; r++)
        *(float4*)&As[(r0 + r) * 128 + c0] =
            make_float4(v[r][0], v[r][1], v[r][2], v[r][3]);
    for (int i = tid; i < 128 * 32; i += 512) {
        int kk = i >> 5, c4 = i & 31;
        float4 w = __ldg((const float4*)Wg + kk * 32 + c4);
        *(float4*)&Bs[kk * 128 + c4 * 4] = w;
    }
    __syncthreads();

    mmtile4<128>(As, Bs, r0, c0, v);
    #pragma unroll
    for (int r = 0; r < 8; r++) {
        int grow = row0 + r0 + r;
        if (grow < NN)
            *(float4*)&g_xw[(size_t)grow * 128 + c0] =
                make_float4(v[r][0], v[r][1], v[r][2], v[r][3]);
    }
}

// ---------------- rep = lrelu(h@Wg1.T+bg1 + lrelu(x@Wl1.T+bl1) + id_emb) ----------------
// 512 threads: half 0 (256 thr) does x@Wl1.T, half 1 does h@Wg1.T; 8x4 microtiles
__global__ void __launch_bounds__(512, 1) k_rep(
    const float* __restrict__ Wl1, const float* __restrict__ bl1,
    const float* __restrict__ Wg1, const float* __restrict__ bg1,
    const float* __restrict__ id_emb, float* __restrict__ rep, int blk0)
{
    extern __shared__ float smx[];
    float* Xs  = smx;            // 128 x 128
    float* Hs  = smx + 16384;    // 128 x 128
    float* W1s = smx + 32768;    // 128 x 64, later epilogue buf
    float* Wgs = smx + 40960;    // 128 x 64
    const int row0 = (blockIdx.x + blk0) * 128;
    int rowlim = NN - row0; if (rowlim > 128) rowlim = 128;
    const int tid = threadIdx.x;

    for (int i = tid; i < 128 * 32; i += 512) {
        int r = i >> 5, c4 = i & 31;
        float4 vx = make_float4(0.f, 0.f, 0.f, 0.f), vh = vx;
        if (r < rowlim) {
            vx = *((const float4*)(g_x + (size_t)(row0 + r) * 128) + c4);
            vh = *((const float4*)(g_h + (size_t)(row0 + r) * 128) + c4);
        }
        *(float4*)&Xs[r * 128 + c4 * 4] = vx;
        *(float4*)&Hs[r * 128 + c4 * 4] = vh;
    }
    for (int i = tid; i < 64 * 32; i += 512) {
        int j = i & 63, c4 = i >> 6;
        float4 v1 = __ldg((const float4*)Wl1 + j * 32 + c4);
        float4 vg = __ldg((const float4*)Wg1 + j * 32 + c4);
        W1s[(c4 * 4 + 0) * 64 + j] = v1.x; W1s[(c4 * 4 + 1) * 64 + j] = v1.y;
        W1s[(c4 * 4 + 2) * 64 + j] = v1.z; W1s[(c4 * 4 + 3) * 64 + j] = v1.w;
        Wgs[(c4 * 4 + 0) * 64 + j] = vg.x; Wgs[(c4 * 4 + 1) * 64 + j] = vg.y;
        Wgs[(c4 * 4 + 2) * 64 + j] = vg.z; Wgs[(c4 * 4 + 3) * 64 + j] = vg.w;
    }
    __syncthreads();

    const int half = tid >> 8, t = tid & 255;
    const int r0 = (t >> 4) * 8, c0 = (t & 15) * 4;
    const float* Ablk = half ? Hs : Xs;
    const float* Wblk = half ? Wgs : W1s;
    float v[8][4];
    mmtile4<64>(Ablk, Wblk, r0, c0, v);
    __syncthreads();

    float* buf = W1s;
    if (half == 0) {
        float4 b0 = __ldg((const float4*)(bl1 + c0));
        float bc[4] = {b0.x, b0.y, b0.z, b0.w};
        #pragma unroll
        for (int r = 0; r < 8; r++) {
            int grow = row0 + r0 + r;
            float4 e0 = make_float4(0.f, 0.f, 0.f, 0.f);
            if (grow < NN)
                e0 = __ldg((const float4*)(id_emb + (size_t)grow * 64 + c0));
            float em[4] = {e0.x, e0.y, e0.z, e0.w};
            #pragma unroll
            for (int c = 0; c < 4; c++)
                buf[(r0 + r) * 64 + c0 + c] = lrelu(v[r][c] + bc[c]) + em[c];
        }
    }
    __syncthreads();
    if (half == 1) {
        float4 b0 = __ldg((const float4*)(bg1 + c0));
        float bc[4] = {b0.x, b0.y, b0.z, b0.w};
        #pragma unroll
        for (int r = 0; r < 8; r++) {
            int grow = row0 + r0 + r;
            if (grow < NN) {
                float o[4];
                #pragma unroll
                for (int c = 0; c < 4; c++)
                    o[c] = lrelu(v[r][c] + bc[c] + buf[(r0 + r) * 64 + c0 + c]);
                *(float4*)&rep[(size_t)grow * 64 + c0] =
                    make_float4(o[0], o[1], o[2], o[3]);
            }
        }
    }
}

// ---------------- batch head ----------------
__global__ void k_batch(const float* __restrict__ rep,
                        const int* __restrict__ un, const int* __restrict__ pit,
                        const int* __restrict__ nit,
                        const float* __restrict__ Wp1, const float* __restrict__ bp1,
                        const float* __restrict__ Wp2, const float* __restrict__ bp2,
                        float* __restrict__ out_pos, float* __restrict__ out_neg,
                        float* __restrict__ out_pred)
{
    int gt = blockIdx.x * 256 + threadIdx.x;
    int w = gt >> 5, lane = gt & 31;
    if (w >= NB) return;
    int iu = __ldg(un + w), ip = __ldg(pit + w), inn = __ldg(nit + w);
    float u0 = __ldg(rep + (size_t)iu * DX + lane), u1 = __ldg(rep + (size_t)iu * DX + 32 + lane);
    float p0 = __ldg(rep + (size_t)ip * DX + lane), p1 = __ldg(rep + (size_t)ip * DX + 32 + lane);
    float n0 = __ldg(rep + (size_t)inn * DX + lane), n1 = __ldg(rep + (size_t)inn * DX + 32 + lane);
    float ps = u0 * p0 + u1 * p1;
    float ns = u0 * n0 + u1 * n1;
    #pragma unroll
    for (int o = 16; o; o >>= 1) {
        ps += __shfl_xor_sync(0xffffffffu, ps, o);
        ns += __shfl_xor_sync(0xffffffffu, ns, o);
    }
    float h0 = __ldg(bp1 + lane), h1 = __ldg(bp1 + lane + 32);
    #pragma unroll 4
    for (int k = 0; k < 128; k++) {
        float srcv = (k < 32) ? u0 : (k < 64) ? u1 : (k < 96) ? p0 : p1;
        float v = __shfl_sync(0xffffffffu, srcv, k & 31);
        h0 += __ldg(Wp1 + lane * 128 + k) * v;
        h1 += __ldg(Wp1 + (lane + 32) * 128 + k) * v;
    }
    h0 = lrelu(h0); h1 = lrelu(h1);
    float pp = __ldg(Wp2 + lane) * h0 + __ldg(Wp2 + lane + 32) * h1;
    #pragma unroll
    for (int o = 16; o; o >>= 1) pp += __shfl_xor_sync(0xffffffffu, pp, o);
    if (lane == 0) {
        out_pos[w] = ps;
        out_neg[w] = ns;
        out_pred[w] = 1.f / (1.f + __expf(-(pp + __ldg(bp2))));
    }
}

// ---------------- launch ----------------
extern "C" void kernel_launch(void* const* d_in, const int* in_sizes, int n_in,
                              void* d_out, int out_size)
{
    const float* feat   = (const float*)d_in[0];
    const float* ufeat  = (const float*)d_in[1];
    const float* Wm     = (const float*)d_in[2];
    const float* bm     = (const float*)d_in[3];
    const float* Wu     = (const float*)d_in[4];
    const float* bu     = (const float*)d_in[5];
    const float* Wgat   = (const float*)d_in[6];
    const float* bgat   = (const float*)d_in[7];
    const float* Wl1    = (const float*)d_in[8];
    const float* bl1    = (const float*)d_in[9];
    const float* Wg1    = (const float*)d_in[10];
    const float* bg1    = (const float*)d_in[11];
    const float* id_emb = (const float*)d_in[12];
    const float* Wp1    = (const float*)d_in[13];
    const float* bp1    = (const float*)d_in[14];
    const float* Wp2    = (const float*)d_in[15];
    const float* bp2    = (const float*)d_in[16];
    const int*   ei     = (const int*)d_in[17];
    const int*   un     = (const int*)d_in[18];
    const int*   pit    = (const int*)d_in[19];
    const int*   nit    = (const int*)d_in[20];

    float* out      = (float*)d_out;
    float* out_pos  = out;
    float* out_neg  = out + NB;
    float* rep      = out + 2 * NB;
    float* out_pred = out + 2 * NB + (size_t)NN * DX;

    static cudaStream_t s_side = nullptr;
    static cudaEvent_t ev_fork = nullptr, ev_join = nullptr, ev_a0 = nullptr, ev_a1 = nullptr;
    if (!s_side) {
        cudaStreamCreateWithFlags(&s_side, cudaStreamNonBlocking);
        cudaEventCreateWithFlags(&ev_fork, cudaEventDisableTiming);
        cudaEventCreateWithFlags(&ev_join, cudaEventDisableTiming);
        cudaEventCreateWithFlags(&ev_a0,   cudaEventDisableTiming);
        cudaEventCreateWithFlags(&ev_a1,   cudaEventDisableTiming);
        cudaFuncSetAttribute(k_gemm_fused, cudaFuncAttributeMaxDynamicSharedMemorySize, 131072);
        cudaFuncSetAttribute(k_rep,        cudaFuncAttributeMaxDynamicSharedMemorySize, 196608);
    }

    // fork: CSR build chain on side stream, GEMM on main stream
    cudaEventRecord(ev_fork, 0);
    cudaStreamWaitEvent(s_side, ev_fork, 0);

    k_zero <<<(NN + 255) / 256, 256, 0, s_side>>>();
    k_hist <<<(NE + 255) / 256, 256, 0, s_side>>>(ei);
    k_scan <<<1, 1024, 0, s_side>>>();
    k_build<<<(NE + 255) / 256, 256, 0, s_side>>>(ei);

    k_gemm_fused<<<782, 512, 131072>>>(feat, ufeat, Wm, bm, Wu, bu, Wgat);

    cudaEventRecord(ev_join, s_side);
    cudaStreamWaitEvent(0, ev_join, 0);

    // pipeline: aggr half0 -> { rep half0 (main) || aggr half1 (side) } -> rep half1
    k_aggr<<<(NSPLIT * 32 + 255) / 256, 256>>>(bgat, 0, NSPLIT);
    cudaEventRecord(ev_a0, 0);
    cudaStreamWaitEvent(s_side, ev_a0, 0);
    k_aggr<<<((NN - NSPLIT) * 32 + 255) / 256, 256, 0, s_side>>>(bgat, NSPLIT, NN - NSPLIT);
    cudaEventRecord(ev_a1, s_side);

    k_rep<<<RBLK0, 512, 196608>>>(Wl1, bl1, Wg1, bg1, id_emb, rep, 0);
    cudaStreamWaitEvent(0, ev_a1, 0);
    k_rep<<<RBLK1, 512, 196608>>>(Wl1, bl1, Wg1, bg1, id_emb, rep, RBLK0);

    k_batch<<<NB / 8, 256>>>(rep, un, pit, nit, Wp1, bp1, Wp2, bp2,
                             out_pos, out_neg, out_pred);
}